// round 2
// baseline (speedup 1.0000x reference)
#include <cuda_runtime.h>
#include <cstdint>
#include <cstddef>

#define BB 128
#define TT 256
#define EMBD 200
#define NU1 400
#define NU2 200

// output layout: out2 | out1 | h2 | h1
#define OUT2_OFF 0
#define OUT1_OFF (BB*TT*NU2)                 // 6553600
#define H2_OFF   (OUT1_OFF + BB*TT*NU1)      // 19660800
#define H1_OFF   (H2_OFF + BB*NU2)           // 19686400

__device__ float g_xn [(size_t)BB*TT*EMBD];
__device__ float g_xw1[(size_t)BB*TT*3*NU1];
__device__ float g_xw2[(size_t)BB*TT*3*NU2];
__device__ float g_h1 [2*BB*NU1];
__device__ float g_h2 [2*BB*NU2];

__global__ void embed_bn(const int* __restrict__ tokens, const float* __restrict__ emb,
                         const float* __restrict__ gamma, const float* __restrict__ beta,
                         const float* __restrict__ mmean, const float* __restrict__ mvar)
{
    int idx = blockIdx.x * blockDim.x + threadIdx.x;
    if (idx >= BB*TT*EMBD) return;
    int d = idx % EMBD;
    int m = idx / EMBD;              // m = t*128 + b
    int b = m & (BB-1), t = m >> 7;
    int tok = tokens[b*TT + t];
    float s = gamma[d] * rsqrtf(mvar[d] + 1e-3f);
    g_xn[idx] = (emb[(size_t)tok*EMBD + d] - mmean[d]) * s + beta[d];
}

__global__ void zero_h()
{
    int i = blockIdx.x * blockDim.x + threadIdx.x;
    if (i < 2*BB*NU1) g_h1[i] = 0.f;
    if (i < 2*BB*NU2) g_h2[i] = 0.f;
}

__global__ void copy_h(const float* __restrict__ src, float* __restrict__ dst, int n)
{
    int i = blockIdx.x * blockDim.x + threadIdx.x;
    if (i < n) dst[i] = src[i];
}

// C[M,N] = A[M,K] @ B[K,N] + bias[N]. M mult of 64, K mult of 8, N guarded.
// GATHER: A row m -> A + ((m&127)*TT + (m>>7))*K   (reads out1 stored [b][t][K])
template<bool GATHER>
__global__ void sgemm(const float* __restrict__ A, const float* __restrict__ Bw,
                      const float* __restrict__ bias, float* __restrict__ C,
                      int N, int K)
{
    __shared__ float As[8][72];
    __shared__ float Bs[8][64];
    const int tid = threadIdx.x;          // 256
    const int row0 = blockIdx.y * 64;
    const int col0 = blockIdx.x * 64;
    const int tx = tid & 15, ty = tid >> 4;
    float acc[4][4] = {};

    for (int k0 = 0; k0 < K; k0 += 8) {
#pragma unroll
        for (int i = tid; i < 512; i += 256) {
            int kk = i & 7, m = i >> 3;
            int gm = row0 + m;
            size_t off = GATHER ? ((size_t)(gm & 127)*TT + (gm >> 7))*(size_t)K + (k0+kk)
                                : (size_t)gm*K + (k0+kk);
            As[kk][m] = A[off];
        }
#pragma unroll
        for (int i = tid; i < 512; i += 256) {
            int kk = i >> 6, n = i & 63;
            int gc = col0 + n;
            Bs[kk][n] = (gc < N) ? Bw[(size_t)(k0+kk)*N + gc] : 0.f;
        }
        __syncthreads();
#pragma unroll
        for (int kk = 0; kk < 8; kk++) {
            float4 a = *reinterpret_cast<const float4*>(&As[kk][ty*4]);
            float4 b = *reinterpret_cast<const float4*>(&Bs[kk][tx*4]);
            float av[4] = {a.x,a.y,a.z,a.w};
            float bv[4] = {b.x,b.y,b.z,b.w};
#pragma unroll
            for (int ii = 0; ii < 4; ii++)
#pragma unroll
                for (int jj = 0; jj < 4; jj++)
                    acc[ii][jj] = fmaf(av[ii], bv[jj], acc[ii][jj]);
        }
        __syncthreads();
    }
#pragma unroll
    for (int ii = 0; ii < 4; ii++) {
        size_t gr = row0 + ty*4 + ii;
#pragma unroll
        for (int jj = 0; jj < 4; jj++) {
            int gc = col0 + tx*4 + jj;
            if (gc < N) C[gr*N + gc] = acc[ii][jj] + bias[gc];
        }
    }
}

// One GRU timestep. grid (ceil(U/32), 8), block 256 = 8 warps x (2 batches each).
// Thread: u = u0+lane, 2 batches, 3 gates, full-K dot products.
template<int UNITS>
__global__ void gru_step(int t, const float* __restrict__ xw, const float* __restrict__ Ur,
                         const float* __restrict__ br, const int* __restrict__ tokens,
                         float* __restrict__ out, float* __restrict__ hping)
{
    __shared__ float sH[16][UNITS + 1];
    const int tid = threadIdx.x;
    const int u0 = blockIdx.x * 32;
    const int b0 = blockIdx.y * 16;
    const float* hg = hping + (t & 1) * (BB*UNITS);
    float* hn = hping + ((t + 1) & 1) * (BB*UNITS);

    for (int i = tid; i < 16*UNITS; i += 256) {
        int bb = i / UNITS, k = i - bb*UNITS;
        sH[bb][k] = hg[(b0 + bb)*UNITS + k];
    }
    __syncthreads();

    const int w = tid >> 5, lane = tid & 31;
    const int u = u0 + lane;
    const int bl = 2*w;
    if (u >= UNITS) return;

    float az0=0,az1=0,ar0=0,ar1=0,ah0=0,ah1=0;
#pragma unroll 4
    for (int k = 0; k < UNITS; k++) {
        float h0 = sH[bl][k], h1 = sH[bl+1][k];
        const float* row = Ur + (size_t)k*3*UNITS;
        float uz = __ldg(row + u);
        float ur = __ldg(row + UNITS + u);
        float uh = __ldg(row + 2*UNITS + u);
        az0 = fmaf(h0, uz, az0); az1 = fmaf(h1, uz, az1);
        ar0 = fmaf(h0, ur, ar0); ar1 = fmaf(h1, ur, ar1);
        ah0 = fmaf(h0, uh, ah0); ah1 = fmaf(h1, uh, ah1);
    }

    const float bz = br[u], brr = br[UNITS+u], bh = br[2*UNITS+u];
#pragma unroll
    for (int j = 0; j < 2; j++) {
        int b = b0 + bl + j;
        float rz = (j ? az1 : az0) + bz;
        float rr = (j ? ar1 : ar0) + brr;
        float rh = (j ? ah1 : ah0) + bh;
        size_t mrow = ((size_t)t*BB + b) * (3*UNITS);
        float xz = xw[mrow + u];
        float xr = xw[mrow + UNITS + u];
        float xh = xw[mrow + 2*UNITS + u];
        float z = 1.f / (1.f + expf(-(xz + rz)));
        float r = 1.f / (1.f + expf(-(xr + rr)));
        float hh = tanhf(xh + r * rh);
        float hold = sH[bl + j][u];
        float hnew = z*hold + (1.f - z)*hh;
        float hv = (tokens[b*TT + t] != 0) ? hnew : hold;
        hn[b*UNITS + u] = hv;
        out[((size_t)b*TT + t)*UNITS + u] = hv;
    }
}

extern "C" void kernel_launch(void* const* d_in, const int* in_sizes, int n_in,
                              void* d_out, int out_size)
{
    const int*   tokens = (const int*)  d_in[0];
    const float* emb    = (const float*)d_in[1];
    const float* gamma  = (const float*)d_in[2];
    const float* beta   = (const float*)d_in[3];
    const float* mmean  = (const float*)d_in[4];
    const float* mvar   = (const float*)d_in[5];
    const float* W1     = (const float*)d_in[6];
    const float* Ur1    = (const float*)d_in[7];
    const float* b1     = (const float*)d_in[8];
    const float* W2     = (const float*)d_in[9];
    const float* Ur2    = (const float*)d_in[10];
    const float* b2     = (const float*)d_in[11];

    float* out  = (float*)d_out;
    float* out2 = out + OUT2_OFF;
    float* out1 = out + OUT1_OFF;
    float* h2o  = out + H2_OFF;
    float* h1o  = out + H1_OFF;

    void *p_xn, *p_xw1, *p_xw2, *p_h1, *p_h2;
    cudaGetSymbolAddress(&p_xn,  g_xn);
    cudaGetSymbolAddress(&p_xw1, g_xw1);
    cudaGetSymbolAddress(&p_xw2, g_xw2);
    cudaGetSymbolAddress(&p_h1,  g_h1);
    cudaGetSymbolAddress(&p_h2,  g_h2);
    float* xn  = (float*)p_xn;
    float* xw1 = (float*)p_xw1;
    float* xw2 = (float*)p_xw2;
    float* h1p = (float*)p_h1;
    float* h2p = (float*)p_h2;

    embed_bn<<<(BB*TT*EMBD + 255)/256, 256>>>(tokens, emb, gamma, beta, mmean, mvar);
    zero_h<<<(2*BB*NU1 + 255)/256, 256>>>();

    // xw1 = xn @ W1 + b1[0]   : [32768,200]x[200,1200]
    sgemm<false><<<dim3((3*NU1 + 63)/64, (BB*TT)/64), 256>>>(xn, W1, b1, xw1, 3*NU1, EMBD);

    for (int t = 0; t < TT; t++)
        gru_step<NU1><<<dim3((NU1 + 31)/32, 8), 256>>>(t, xw1, Ur1, b1 + 3*NU1, tokens, out1, h1p);

    copy_h<<<(BB*NU1 + 255)/256, 256>>>(h1p, h1o, BB*NU1);   // T even -> final in buf 0

    // xw2 = out1 @ W2 + b2[0] : gather rows from out1 [b][t][400]
    sgemm<true><<<dim3((3*NU2 + 63)/64, (BB*TT)/64), 256>>>(out1, W2, b2, xw2, 3*NU2, NU1);

    for (int t = 0; t < TT; t++)
        gru_step<NU2><<<dim3((NU2 + 31)/32, 8), 256>>>(t, xw2, Ur2, b2 + 3*NU2, tokens, out2, h2p);

    copy_h<<<(BB*NU2 + 255)/256, 256>>>(h2p, h2o, BB*NU2);
}

// round 3
// speedup vs baseline: 2.3661x; 2.3661x over previous
#include <cuda_runtime.h>
#include <cstdint>
#include <cstddef>

#define BB 128
#define TT 256
#define EMBD 200
#define NU1 400
#define NU2 200

// output layout: out2 | out1 | h2 | h1
#define OUT2_OFF 0
#define OUT1_OFF (BB*TT*NU2)
#define H2_OFF   (OUT1_OFF + BB*TT*NU1)
#define H1_OFF   (H2_OFF + BB*NU2)

__device__ float g_xn [(size_t)BB*TT*EMBD];
__device__ float g_xw1[(size_t)BB*TT*3*NU1];
__device__ float g_xw2[(size_t)BB*TT*3*NU2];
__device__ float g_h1 [2*BB*NU1];
__device__ float g_h2 [2*BB*NU2];

__global__ void embed_bn(const int* __restrict__ tokens, const float* __restrict__ emb,
                         const float* __restrict__ gamma, const float* __restrict__ beta,
                         const float* __restrict__ mmean, const float* __restrict__ mvar)
{
    int idx = blockIdx.x * blockDim.x + threadIdx.x;
    if (idx >= BB*TT*EMBD) return;
    int d = idx % EMBD;
    int m = idx / EMBD;              // m = t*128 + b
    int b = m & (BB-1), t = m >> 7;
    int tok = tokens[b*TT + t];
    float s = gamma[d] * rsqrtf(mvar[d] + 1e-3f);
    g_xn[idx] = (emb[(size_t)tok*EMBD + d] - mmean[d]) * s + beta[d];
}

__global__ void zero_h()
{
    int i = blockIdx.x * blockDim.x + threadIdx.x;
    if (i < 2*BB*NU1) g_h1[i] = 0.f;
    if (i < 2*BB*NU2) g_h2[i] = 0.f;
}

__global__ void copy_h(const float* __restrict__ src, float* __restrict__ dst, int n)
{
    int i = blockIdx.x * blockDim.x + threadIdx.x;
    if (i < n) dst[i] = src[i];
}

// C[M,N] = A[M,K] @ B[K,N] + bias[N]. M mult of 64, K mult of 8, N guarded.
// GATHER: A row m -> A + ((m&127)*TT + (m>>7))*K   (reads out1 stored [b][t][K])
template<bool GATHER>
__global__ void sgemm(const float* __restrict__ A, const float* __restrict__ Bw,
                      const float* __restrict__ bias, float* __restrict__ C,
                      int N, int K)
{
    __shared__ float As[8][72];
    __shared__ float Bs[8][64];
    const int tid = threadIdx.x;          // 256
    const int row0 = blockIdx.y * 64;
    const int col0 = blockIdx.x * 64;
    const int tx = tid & 15, ty = tid >> 4;
    float acc[4][4] = {};

    for (int k0 = 0; k0 < K; k0 += 8) {
#pragma unroll
        for (int i = tid; i < 512; i += 256) {
            int kk = i & 7, m = i >> 3;
            int gm = row0 + m;
            size_t off = GATHER ? ((size_t)(gm & 127)*TT + (gm >> 7))*(size_t)K + (k0+kk)
                                : (size_t)gm*K + (k0+kk);
            As[kk][m] = A[off];
        }
#pragma unroll
        for (int i = tid; i < 512; i += 256) {
            int kk = i >> 6, n = i & 63;
            int gc = col0 + n;
            Bs[kk][n] = (gc < N) ? Bw[(size_t)(k0+kk)*N + gc] : 0.f;
        }
        __syncthreads();
#pragma unroll
        for (int kk = 0; kk < 8; kk++) {
            float4 a = *reinterpret_cast<const float4*>(&As[kk][ty*4]);
            float4 b = *reinterpret_cast<const float4*>(&Bs[kk][tx*4]);
            float av[4] = {a.x,a.y,a.z,a.w};
            float bv[4] = {b.x,b.y,b.z,b.w};
#pragma unroll
            for (int ii = 0; ii < 4; ii++)
#pragma unroll
                for (int jj = 0; jj < 4; jj++)
                    acc[ii][jj] = fmaf(av[ii], bv[jj], acc[ii][jj]);
        }
        __syncthreads();
    }
#pragma unroll
    for (int ii = 0; ii < 4; ii++) {
        size_t gr = row0 + ty*4 + ii;
#pragma unroll
        for (int jj = 0; jj < 4; jj++) {
            int gc = col0 + tx*4 + jj;
            if (gc < N) C[gr*N + gc] = acc[ii][jj] + bias[gc];
        }
    }
}

// ---------------- GRU timestep as smem GEMM ----------------
// CTA tile: BT batches x UT units x 3 gates. THREADS = UT * BT/2.
// Thread (uu = tid%UT, bg = tid/UT) computes (unit u0+uu) x (batches b0+2bg, +1) x 3 gates.
// K staged in chunks of KC=50: sH [BT][KC], sU [KC][3*UT]. Inner loop: 5 LDS + 6 FFMA.
template<int UNITS, int UT, int BT, int THREADS>
__global__ void __launch_bounds__(THREADS)
gru_step(int t, const float* __restrict__ xw, const float* __restrict__ Ur,
         const float* __restrict__ br, const int* __restrict__ tokens,
         float* __restrict__ out, float* __restrict__ hping)
{
    constexpr int KC = 50;                 // UNITS % 50 == 0 for 400 and 200
    constexpr int COLS = 3*UT;
    __shared__ float sH[BT][KC];
    __shared__ float sU[KC][COLS];

    const int tid = threadIdx.x;
    const int u0 = blockIdx.x * UT;
    const int b0 = blockIdx.y * BT;
    const float* hg = hping + (t & 1) * (BB*UNITS);
    float* hn = hping + ((t + 1) & 1) * (BB*UNITS);

    const int uu = tid % UT;
    const int bg = tid / UT;
    const int b2 = 2*bg;

    float az0=0,az1=0,ar0=0,ar1=0,ah0=0,ah1=0;

    for (int k0 = 0; k0 < UNITS; k0 += KC) {
#pragma unroll
        for (int i = tid; i < BT*KC; i += THREADS) {
            int bb = i / KC, kk = i - bb*KC;
            sH[bb][kk] = hg[(size_t)(b0+bb)*UNITS + k0 + kk];
        }
#pragma unroll
        for (int i = tid; i < KC*COLS; i += THREADS) {
            int kk = i / COLS, c = i - kk*COLS;
            int g = c / UT, uux = c - g*UT;
            sU[kk][c] = Ur[(size_t)(k0+kk)*(3*UNITS) + g*UNITS + u0 + uux];
        }
        __syncthreads();
#pragma unroll
        for (int kk = 0; kk < KC; kk++) {
            float h0 = sH[b2][kk];
            float h1 = sH[b2+1][kk];
            float uz = sU[kk][uu];
            float ur = sU[kk][UT + uu];
            float uh = sU[kk][2*UT + uu];
            az0 = fmaf(h0, uz, az0); az1 = fmaf(h1, uz, az1);
            ar0 = fmaf(h0, ur, ar0); ar1 = fmaf(h1, ur, ar1);
            ah0 = fmaf(h0, uh, ah0); ah1 = fmaf(h1, uh, ah1);
        }
        __syncthreads();
    }

    const int u = u0 + uu;
    const float bz = br[u], brr = br[UNITS+u], bh = br[2*UNITS+u];
#pragma unroll
    for (int j = 0; j < 2; j++) {
        int b = b0 + b2 + j;
        float rz = (j ? az1 : az0) + bz;
        float rr = (j ? ar1 : ar0) + brr;
        float rh = (j ? ah1 : ah0) + bh;
        size_t mrow = ((size_t)t*BB + b) * (3*UNITS);
        float xz = xw[mrow + u];
        float xr = xw[mrow + UNITS + u];
        float xh = xw[mrow + 2*UNITS + u];
        float z = 1.f / (1.f + expf(-(xz + rz)));
        float r = 1.f / (1.f + expf(-(xr + rr)));
        float hh = tanhf(xh + r * rh);
        float hold = hg[(size_t)b*UNITS + u];
        float hnew = z*hold + (1.f - z)*hh;
        float hv = (tokens[b*TT + t] != 0) ? hnew : hold;
        hn[(size_t)b*UNITS + u] = hv;
        out[((size_t)b*TT + t)*UNITS + u] = hv;
    }
}

extern "C" void kernel_launch(void* const* d_in, const int* in_sizes, int n_in,
                              void* d_out, int out_size)
{
    const int*   tokens = (const int*)  d_in[0];
    const float* emb    = (const float*)d_in[1];
    const float* gamma  = (const float*)d_in[2];
    const float* beta   = (const float*)d_in[3];
    const float* mmean  = (const float*)d_in[4];
    const float* mvar   = (const float*)d_in[5];
    const float* W1     = (const float*)d_in[6];
    const float* Ur1    = (const float*)d_in[7];
    const float* b1     = (const float*)d_in[8];
    const float* W2     = (const float*)d_in[9];
    const float* Ur2    = (const float*)d_in[10];
    const float* b2     = (const float*)d_in[11];

    float* out  = (float*)d_out;
    float* out2 = out + OUT2_OFF;
    float* out1 = out + OUT1_OFF;
    float* h2o  = out + H2_OFF;
    float* h1o  = out + H1_OFF;

    void *p_xn, *p_xw1, *p_xw2, *p_h1, *p_h2;
    cudaGetSymbolAddress(&p_xn,  g_xn);
    cudaGetSymbolAddress(&p_xw1, g_xw1);
    cudaGetSymbolAddress(&p_xw2, g_xw2);
    cudaGetSymbolAddress(&p_h1,  g_h1);
    cudaGetSymbolAddress(&p_h2,  g_h2);
    float* xn  = (float*)p_xn;
    float* xw1 = (float*)p_xw1;
    float* xw2 = (float*)p_xw2;
    float* h1p = (float*)p_h1;
    float* h2p = (float*)p_h2;

    embed_bn<<<(BB*TT*EMBD + 255)/256, 256>>>(tokens, emb, gamma, beta, mmean, mvar);
    zero_h<<<(2*BB*NU1 + 255)/256, 256>>>();

    // xw1 = xn @ W1 + b1[0]   : [32768,200]x[200,1200]
    sgemm<false><<<dim3((3*NU1 + 63)/64, (BB*TT)/64), 256>>>(xn, W1, b1, xw1, 3*NU1, EMBD);

    // layer 1: UT=16, BT=32 -> grid (25,4), 256 threads
    for (int t = 0; t < TT; t++)
        gru_step<NU1, 16, 32, 256><<<dim3(NU1/16, BB/32), 256>>>(
            t, xw1, Ur1, b1 + 3*NU1, tokens, out1, h1p);

    copy_h<<<(BB*NU1 + 255)/256, 256>>>(h1p, h1o, BB*NU1);   // T even -> final in buf 0

    // xw2 = out1 @ W2 + b2[0] : gather rows from out1 [b][t][400]
    sgemm<true><<<dim3((3*NU2 + 63)/64, (BB*TT)/64), 256>>>(out1, W2, b2, xw2, 3*NU2, NU1);

    // layer 2: UT=8, BT=32 -> grid (25,4), 128 threads
    for (int t = 0; t < TT; t++)
        gru_step<NU2, 8, 32, 128><<<dim3(NU2/8, BB/32), 128>>>(
            t, xw2, Ur2, b2 + 3*NU2, tokens, out2, h2p);

    copy_h<<<(BB*NU2 + 255)/256, 256>>>(h2p, h2o, BB*NU2);
}

// round 4
// speedup vs baseline: 2.5304x; 1.0694x over previous
#include <cuda_runtime.h>
#include <cstdint>
#include <cstddef>

#define BB 128
#define TT 256
#define EMBD 200
#define NU1 400
#define NU2 200

// output layout: out2 | out1 | h2 | h1
#define OUT2_OFF 0
#define OUT1_OFF (BB*TT*NU2)
#define H2_OFF   (OUT1_OFF + BB*TT*NU1)
#define H1_OFF   (H2_OFF + BB*NU2)

__device__ float g_xn [(size_t)BB*TT*EMBD];
__device__ float g_xw1[(size_t)BB*TT*3*NU1];
__device__ float g_xw2[(size_t)BB*TT*3*NU2];
__device__ float g_h1 [2*BB*NU1];
__device__ float g_h2 [2*BB*NU2];
__device__ unsigned g_cnt1, g_gen1, g_cnt2, g_gen2;

__global__ void embed_bn(const int* __restrict__ tokens, const float* __restrict__ emb,
                         const float* __restrict__ gamma, const float* __restrict__ beta,
                         const float* __restrict__ mmean, const float* __restrict__ mvar)
{
    int idx = blockIdx.x * blockDim.x + threadIdx.x;
    if (idx >= BB*TT*EMBD) return;
    int d = idx % EMBD;
    int m = idx / EMBD;              // m = t*128 + b
    int b = m & (BB-1), t = m >> 7;
    int tok = tokens[b*TT + t];
    float s = gamma[d] * rsqrtf(mvar[d] + 1e-3f);
    g_xn[idx] = (emb[(size_t)tok*EMBD + d] - mmean[d]) * s + beta[d];
}

__global__ void init_state()
{
    int i = blockIdx.x * blockDim.x + threadIdx.x;
    if (i < 2*BB*NU1) g_h1[i] = 0.f;
    if (i < 2*BB*NU2) g_h2[i] = 0.f;
    if (i == 0) { g_cnt1 = 0; g_gen1 = 0; g_cnt2 = 0; g_gen2 = 0; }
}

__global__ void copy_h(const float* __restrict__ src, float* __restrict__ dst, int n)
{
    int i = blockIdx.x * blockDim.x + threadIdx.x;
    if (i < n) dst[i] = src[i];
}

// C[M,N] = A[M,K] @ B[K,N] + bias[N]. M mult of 64, K mult of 8, N guarded.
// GATHER: A row m -> A + ((m&127)*TT + (m>>7))*K   (reads out1 stored [b][t][K])
template<bool GATHER>
__global__ void sgemm(const float* __restrict__ A, const float* __restrict__ Bw,
                      const float* __restrict__ bias, float* __restrict__ C,
                      int N, int K)
{
    __shared__ float As[8][72];
    __shared__ float Bs[8][64];
    const int tid = threadIdx.x;          // 256
    const int row0 = blockIdx.y * 64;
    const int col0 = blockIdx.x * 64;
    const int tx = tid & 15, ty = tid >> 4;
    float acc[4][4] = {};

    for (int k0 = 0; k0 < K; k0 += 8) {
#pragma unroll
        for (int i = tid; i < 512; i += 256) {
            int kk = i & 7, m = i >> 3;
            int gm = row0 + m;
            size_t off = GATHER ? ((size_t)(gm & 127)*TT + (gm >> 7))*(size_t)K + (k0+kk)
                                : (size_t)gm*K + (k0+kk);
            As[kk][m] = A[off];
        }
#pragma unroll
        for (int i = tid; i < 512; i += 256) {
            int kk = i >> 6, n = i & 63;
            int gc = col0 + n;
            Bs[kk][n] = (gc < N) ? Bw[(size_t)(k0+kk)*N + gc] : 0.f;
        }
        __syncthreads();
#pragma unroll
        for (int kk = 0; kk < 8; kk++) {
            float4 a = *reinterpret_cast<const float4*>(&As[kk][ty*4]);
            float4 b = *reinterpret_cast<const float4*>(&Bs[kk][tx*4]);
            float av[4] = {a.x,a.y,a.z,a.w};
            float bv[4] = {b.x,b.y,b.z,b.w};
#pragma unroll
            for (int ii = 0; ii < 4; ii++)
#pragma unroll
                for (int jj = 0; jj < 4; jj++)
                    acc[ii][jj] = fmaf(av[ii], bv[jj], acc[ii][jj]);
        }
        __syncthreads();
    }
#pragma unroll
    for (int ii = 0; ii < 4; ii++) {
        size_t gr = row0 + ty*4 + ii;
#pragma unroll
        for (int jj = 0; jj < 4; jj++) {
            int gc = col0 + tx*4 + jj;
            if (gc < N) C[gr*N + gc] = acc[ii][jj] + bias[gc];
        }
    }
}

// grid-wide barrier (all CTAs co-resident by construction)
__device__ __forceinline__ void grid_barrier(unsigned* cnt, volatile unsigned* gen,
                                             unsigned target, int nctas)
{
    __threadfence();
    __syncthreads();
    if (threadIdx.x == 0) {
        unsigned arr = atomicAdd(cnt, 1u);
        if (arr == (unsigned)(nctas - 1)) {
            *cnt = 0;
            __threadfence();
            *gen = target;
        } else {
            while (*gen < target) { }
            __threadfence();
        }
    }
    __syncthreads();
}

// ---------------- persistent GRU layer ----------------
// grid (UNITS/25, BB/BT), block NTHR = 25*BT. U slice resident in smem for all T steps.
// Thread (uu = tid%25, bl = tid/25) owns unit u0+uu, batch b0+bl, 3 gates.
// h passes between CTAs through L2 (st.cg / ld.cg).
template<int UNITS, int BT, int NTHR, int NCTAS>
__global__ void __launch_bounds__(NTHR, 1)
gru_layer(const float* __restrict__ xw, const float* __restrict__ Ur,
          const float* __restrict__ br, const int* __restrict__ tokens,
          float* __restrict__ out, float* __restrict__ hping,
          unsigned* cnt, unsigned* gen)
{
    constexpr int KP = UNITS + 4;          // padded row stride (words)
    extern __shared__ float sm[];
    float* sU = sm;                        // [75][KP]  (cols: z 0..24 | r 25..49 | h 50..74)
    float* sH = sm + 75*KP;                // [BT][KP]

    const int tid = threadIdx.x;
    const int u0  = blockIdx.x * 25;
    const int b0  = blockIdx.y * BT;
    const int uu  = tid % 25;
    const int bl  = tid / 25;
    const int u   = u0 + uu;
    const int b   = b0 + bl;

    // one-time: load U slice (transposed to [col][k]) — coalesced over gate segments
    for (int i = tid; i < 75*UNITS; i += NTHR) {
        int c = i % 75, k = i / 75;
        int g = c / 25, ux = c - g*25;
        sU[c*KP + k] = Ur[(size_t)k*(3*UNITS) + g*UNITS + u0 + ux];
    }

    const float bz  = br[u];
    const float brr = br[UNITS + u];
    const float bh  = br[2*UNITS + u];
    const float* uzp = sU + uu*KP;
    const float* urp = sU + (25+uu)*KP;
    const float* uhp = sU + (50+uu)*KP;
    const float* hrow = sH + bl*KP;

    for (int t = 0; t < TT; t++) {
        const float* hg = hping + (t & 1) * (BB*UNITS);
        float*       hn = hping + ((t + 1) & 1) * (BB*UNITS);

        // prefetch x-projections + mask (independent of h -> hidden under compute)
        size_t mrow = ((size_t)t*BB + b) * (size_t)(3*UNITS);
        float xz = __ldg(xw + mrow + u);
        float xr = __ldg(xw + mrow + UNITS + u);
        float xh = __ldg(xw + mrow + 2*UNITS + u);
        int   mk = tokens[b*TT + t];

        // stage h tile [BT][UNITS] from L2
        for (int i = tid; i < BT*UNITS; i += NTHR) {
            int bb = i / UNITS, k = i - bb*UNITS;
            sH[bb*KP + k] = __ldcg(hg + (size_t)(b0+bb)*UNITS + k);
        }
        __syncthreads();

        float az = 0.f, ar = 0.f, ah = 0.f;
#pragma unroll 4
        for (int k = 0; k < UNITS; k += 4) {
            float4 h4 = *reinterpret_cast<const float4*>(hrow + k);
            float4 z4 = *reinterpret_cast<const float4*>(uzp + k);
            float4 r4 = *reinterpret_cast<const float4*>(urp + k);
            float4 c4 = *reinterpret_cast<const float4*>(uhp + k);
            az = fmaf(h4.x, z4.x, az); az = fmaf(h4.y, z4.y, az);
            az = fmaf(h4.z, z4.z, az); az = fmaf(h4.w, z4.w, az);
            ar = fmaf(h4.x, r4.x, ar); ar = fmaf(h4.y, r4.y, ar);
            ar = fmaf(h4.z, r4.z, ar); ar = fmaf(h4.w, r4.w, ar);
            ah = fmaf(h4.x, c4.x, ah); ah = fmaf(h4.y, c4.y, ah);
            ah = fmaf(h4.z, c4.z, ah); ah = fmaf(h4.w, c4.w, ah);
        }

        float z  = 1.f / (1.f + __expf(-(xz + az + bz)));
        float r  = 1.f / (1.f + __expf(-(xr + ar + brr)));
        float hh = tanhf(xh + r * (ah + bh));
        float hold = hrow[u];                       // own unit's old h from staged tile
        float hnew = z*hold + (1.f - z)*hh;
        float hv = (mk != 0) ? hnew : hold;

        __stcg(hn + (size_t)b*UNITS + u, hv);
        out[((size_t)b*TT + t)*UNITS + u] = hv;

        grid_barrier(cnt, gen, (unsigned)(t + 1), NCTAS);
    }
}

extern "C" void kernel_launch(void* const* d_in, const int* in_sizes, int n_in,
                              void* d_out, int out_size)
{
    const int*   tokens = (const int*)  d_in[0];
    const float* emb    = (const float*)d_in[1];
    const float* gamma  = (const float*)d_in[2];
    const float* beta   = (const float*)d_in[3];
    const float* mmean  = (const float*)d_in[4];
    const float* mvar   = (const float*)d_in[5];
    const float* W1     = (const float*)d_in[6];
    const float* Ur1    = (const float*)d_in[7];
    const float* b1     = (const float*)d_in[8];
    const float* W2     = (const float*)d_in[9];
    const float* Ur2    = (const float*)d_in[10];
    const float* b2     = (const float*)d_in[11];

    float* out  = (float*)d_out;
    float* out2 = out + OUT2_OFF;
    float* out1 = out + OUT1_OFF;
    float* h2o  = out + H2_OFF;
    float* h1o  = out + H1_OFF;

    void *p_xn, *p_xw1, *p_xw2, *p_h1, *p_h2, *p_c1, *p_g1, *p_c2, *p_g2;
    cudaGetSymbolAddress(&p_xn,  g_xn);
    cudaGetSymbolAddress(&p_xw1, g_xw1);
    cudaGetSymbolAddress(&p_xw2, g_xw2);
    cudaGetSymbolAddress(&p_h1,  g_h1);
    cudaGetSymbolAddress(&p_h2,  g_h2);
    cudaGetSymbolAddress(&p_c1,  g_cnt1);
    cudaGetSymbolAddress(&p_g1,  g_gen1);
    cudaGetSymbolAddress(&p_c2,  g_cnt2);
    cudaGetSymbolAddress(&p_g2,  g_gen2);
    float* xn  = (float*)p_xn;
    float* xw1 = (float*)p_xw1;
    float* xw2 = (float*)p_xw2;
    float* h1p = (float*)p_h1;
    float* h2p = (float*)p_h2;

    // persistent-layer shapes
    constexpr int L1_BT = 16, L1_THR = 25*L1_BT;          // 400 threads
    constexpr int L1_NC = (NU1/25) * (BB/L1_BT);          // 16*8 = 128 CTAs
    constexpr int L1_SMEM = (75*(NU1+4) + L1_BT*(NU1+4)) * 4;   // ~147KB
    constexpr int L2_BT = 8,  L2_THR = 25*L2_BT;          // 200 threads
    constexpr int L2_NC = (NU2/25) * (BB/L2_BT);          // 8*16 = 128 CTAs
    constexpr int L2_SMEM = (75*(NU2+4) + L2_BT*(NU2+4)) * 4;   // ~68KB

    cudaFuncSetAttribute(gru_layer<NU1, L1_BT, L1_THR, L1_NC>,
                         cudaFuncAttributeMaxDynamicSharedMemorySize, L1_SMEM);
    cudaFuncSetAttribute(gru_layer<NU2, L2_BT, L2_THR, L2_NC>,
                         cudaFuncAttributeMaxDynamicSharedMemorySize, L2_SMEM);

    embed_bn<<<(BB*TT*EMBD + 255)/256, 256>>>(tokens, emb, gamma, beta, mmean, mvar);
    init_state<<<(2*BB*NU1 + 255)/256, 256>>>();

    // xw1 = xn @ W1 + b1[0]   : [32768,200]x[200,1200]
    sgemm<false><<<dim3((3*NU1 + 63)/64, (BB*TT)/64), 256>>>(xn, W1, b1, xw1, 3*NU1, EMBD);

    // layer 1 persistent: grid (16,8) = 128 CTAs, 400 threads
    gru_layer<NU1, L1_BT, L1_THR, L1_NC>
        <<<dim3(NU1/25, BB/L1_BT), L1_THR, L1_SMEM>>>(
            xw1, Ur1, b1 + 3*NU1, tokens, out1, h1p, (unsigned*)p_c1, (unsigned*)p_g1);

    copy_h<<<(BB*NU1 + 255)/256, 256>>>(h1p, h1o, BB*NU1);   // T even -> final in buf 0

    // xw2 = out1 @ W2 + b2[0] : gather rows from out1 [b][t][400]
    sgemm<true><<<dim3((3*NU2 + 63)/64, (BB*TT)/64), 256>>>(out1, W2, b2, xw2, 3*NU2, NU1);

    // layer 2 persistent: grid (8,16) = 128 CTAs, 200 threads
    gru_layer<NU2, L2_BT, L2_THR, L2_NC>
        <<<dim3(NU2/25, BB/L2_BT), L2_THR, L2_SMEM>>>(
            xw2, Ur2, b2 + 3*NU2, tokens, out2, h2p, (unsigned*)p_c2, (unsigned*)p_g2);

    copy_h<<<(BB*NU2 + 255)/256, 256>>>(h2p, h2o, BB*NU2);
}

// round 5
// speedup vs baseline: 2.6220x; 1.0362x over previous
#include <cuda_runtime.h>
#include <cstdint>
#include <cstddef>

#define BB 128
#define TT 256
#define EMBD 200
#define NU1 400
#define NU2 200

// output layout: out2 | out1 | h2 | h1
#define OUT2_OFF 0
#define OUT1_OFF (BB*TT*NU2)
#define H2_OFF   (OUT1_OFF + BB*TT*NU1)
#define H1_OFF   (H2_OFF + BB*NU2)

__device__ float g_xn [(size_t)BB*TT*EMBD];
__device__ float g_xw1[(size_t)BB*TT*3*NU1];
__device__ float g_xw2[(size_t)BB*TT*3*NU2];
__device__ float g_h1 [2*BB*NU1];
__device__ float g_h2 [2*BB*NU2];
// barrier state, padded to 128B per group
__device__ unsigned g_cnt1[4*32], g_gen1[4*32], g_cnt2[4*32], g_gen2[4*32];

__global__ void embed_bn(const int* __restrict__ tokens, const float* __restrict__ emb,
                         const float* __restrict__ gamma, const float* __restrict__ beta,
                         const float* __restrict__ mmean, const float* __restrict__ mvar)
{
    int idx = blockIdx.x * blockDim.x + threadIdx.x;
    if (idx >= BB*TT*EMBD) return;
    int d = idx % EMBD;
    int m = idx / EMBD;              // m = t*128 + b
    int b = m & (BB-1), t = m >> 7;
    int tok = tokens[b*TT + t];
    float s = gamma[d] * rsqrtf(mvar[d] + 1e-3f);
    g_xn[idx] = (emb[(size_t)tok*EMBD + d] - mmean[d]) * s + beta[d];
}

__global__ void init_state()
{
    int i = blockIdx.x * blockDim.x + threadIdx.x;
    if (i < 2*BB*NU1) g_h1[i] = 0.f;
    if (i < 2*BB*NU2) g_h2[i] = 0.f;
    if (i < 4*32) { g_cnt1[i] = 0; g_gen1[i] = 0; g_cnt2[i] = 0; g_gen2[i] = 0; }
}

__global__ void copy_h(const float* __restrict__ src, float* __restrict__ dst, int n)
{
    int i = blockIdx.x * blockDim.x + threadIdx.x;
    if (i < n) dst[i] = src[i];
}

// C[M,N] = A[M,K] @ B[K,N] + bias[N]. M mult of 64, K mult of 8, N guarded.
// GATHER: A row m -> A + ((m&127)*TT + (m>>7))*K   (reads out1 stored [b][t][K])
template<bool GATHER>
__global__ void sgemm(const float* __restrict__ A, const float* __restrict__ Bw,
                      const float* __restrict__ bias, float* __restrict__ C,
                      int N, int K)
{
    __shared__ float As[8][72];
    __shared__ float Bs[8][64];
    const int tid = threadIdx.x;          // 256
    const int row0 = blockIdx.y * 64;
    const int col0 = blockIdx.x * 64;
    const int tx = tid & 15, ty = tid >> 4;
    float acc[4][4] = {};

    for (int k0 = 0; k0 < K; k0 += 8) {
#pragma unroll
        for (int i = tid; i < 512; i += 256) {
            int kk = i & 7, m = i >> 3;
            int gm = row0 + m;
            size_t off = GATHER ? ((size_t)(gm & 127)*TT + (gm >> 7))*(size_t)K + (k0+kk)
                                : (size_t)gm*K + (k0+kk);
            As[kk][m] = A[off];
        }
#pragma unroll
        for (int i = tid; i < 512; i += 256) {
            int kk = i >> 6, n = i & 63;
            int gc = col0 + n;
            Bs[kk][n] = (gc < N) ? Bw[(size_t)(k0+kk)*N + gc] : 0.f;
        }
        __syncthreads();
#pragma unroll
        for (int kk = 0; kk < 8; kk++) {
            float4 a = *reinterpret_cast<const float4*>(&As[kk][ty*4]);
            float4 b = *reinterpret_cast<const float4*>(&Bs[kk][tx*4]);
            float av[4] = {a.x,a.y,a.z,a.w};
            float bv[4] = {b.x,b.y,b.z,b.w};
#pragma unroll
            for (int ii = 0; ii < 4; ii++)
#pragma unroll
                for (int jj = 0; jj < 4; jj++)
                    acc[ii][jj] = fmaf(av[ii], bv[jj], acc[ii][jj]);
        }
        __syncthreads();
    }
#pragma unroll
    for (int ii = 0; ii < 4; ii++) {
        size_t gr = row0 + ty*4 + ii;
#pragma unroll
        for (int jj = 0; jj < 4; jj++) {
            int gc = col0 + tx*4 + jj;
            if (gc < N) C[gr*N + gc] = acc[ii][jj] + bias[gc];
        }
    }
}

// packed f32x2 fma (sm_10x)
__device__ __forceinline__ unsigned long long fma2(unsigned long long a, unsigned long long b,
                                                   unsigned long long c)
{
    unsigned long long d;
    asm("fma.rn.f32x2 %0, %1, %2, %3;" : "=l"(d) : "l"(a), "l"(b), "l"(c));
    return d;
}
__device__ __forceinline__ float hsum2(unsigned long long a)
{
    float2 f = *reinterpret_cast<float2*>(&a);
    return f.x + f.y;
}

// ---------------- persistent GRU layer ----------------
// grid (UNITS/UT, BB/32). CTA: UT units x 32 batches. Warp = UW units x 32 batches (lane=batch).
// U slice in smem forever (broadcast loads); h exchanged via L2; barrier per batch-group.
template<int UNITS, int UT, int UW, int GROUP_CTAS>
__global__ void __launch_bounds__(32*UT/UW, 1)
gru_layer(const float* __restrict__ xw, const float* __restrict__ Ur,
          const float* __restrict__ br, const int* __restrict__ tokens,
          float* __restrict__ out, float* __restrict__ hping,
          unsigned* cnt, unsigned* gen)
{
    constexpr int NTHR = 32*UT/UW;
    constexpr int KP = UNITS + 4;       // KP/4 odd -> conflict-free LDS.128 by lane
    constexpr int XS = 3*UT + 1;
    extern __shared__ float sm[];
    float* sU   = sm;                   // [UT*3][KP], row (lu*3+g)
    float* sH   = sU + UT*3*KP;         // [32][KP]
    float* sX   = sH + 32*KP;           // [32][XS]
    int*   sTok = (int*)(sX + 32*XS);   // [32][TT+1]

    const int tid  = threadIdx.x;
    const int w    = tid >> 5;
    const int lane = tid & 31;
    const int u0   = blockIdx.x * UT;
    const int b0   = blockIdx.y * 32;
    const int grp  = blockIdx.y;
    const int b    = b0 + lane;
    const int uu0  = u0 + w*UW;         // first global unit of this thread

    // one-time: U slice -> smem, transposed to [unit][gate][k]
    for (int i = tid; i < 3*UT*UNITS; i += NTHR) {
        int k = i / (3*UT), c = i % (3*UT);
        int g = c / UT, lu = c % UT;
        sU[(lu*3 + g)*KP + k] = Ur[(size_t)k*(3*UNITS) + g*UNITS + u0 + lu];
    }
    // one-time: tokens for this batch tile
    for (int i = tid; i < 32*TT; i += NTHR) {
        int bb = i / TT, tt = i % TT;
        sTok[bb*(TT+1) + tt] = tokens[(b0 + bb)*TT + tt];
    }
    // per-thread constant biases
    float bz[UW], brr[UW], bh[UW];
#pragma unroll
    for (int j = 0; j < UW; j++) {
        bz[j]  = br[uu0 + j];
        brr[j] = br[UNITS + uu0 + j];
        bh[j]  = br[2*UNITS + uu0 + j];
    }

    const float* hrow = sH + lane*KP;

    for (int t = 0; t < TT; t++) {
        const float* hg = hping + (t & 1) * (BB*UNITS);
        float*       hn = hping + ((t + 1) & 1) * (BB*UNITS);

        // stage xw tile [32][3*UT] (coalesced 64B segments)
        for (int i = tid; i < 32*3*UT; i += NTHR) {
            int bb = i / (3*UT), c = i % (3*UT);
            int g = c / UT, lu = c % UT;
            sX[bb*XS + c] = __ldg(xw + ((size_t)t*BB + b0 + bb)*(size_t)(3*UNITS)
                                      + (size_t)g*UNITS + u0 + lu);
        }
        // stage h tile [32][UNITS] from L2 (vectorized)
        for (int i = tid; i < 32*(UNITS/4); i += NTHR) {
            int bb = i / (UNITS/4), kk = i % (UNITS/4);
            float4 v = __ldcg(reinterpret_cast<const float4*>(hg + (size_t)(b0+bb)*UNITS) + kk);
            *reinterpret_cast<float4*>(&sH[bb*KP + kk*4]) = v;
        }
        __syncthreads();

        unsigned long long az[UW] = {}, ar[UW] = {}, ah[UW] = {};
#pragma unroll 2
        for (int k = 0; k < UNITS; k += 4) {
            ulonglong2 h2 = *reinterpret_cast<const ulonglong2*>(hrow + k);
#pragma unroll
            for (int j = 0; j < UW; j++) {
                const float* ub = sU + ((w*UW + j)*3)*KP + k;
                ulonglong2 uz = *reinterpret_cast<const ulonglong2*>(ub);
                ulonglong2 ur = *reinterpret_cast<const ulonglong2*>(ub + KP);
                ulonglong2 uh = *reinterpret_cast<const ulonglong2*>(ub + 2*KP);
                az[j] = fma2(h2.x, uz.x, az[j]); az[j] = fma2(h2.y, uz.y, az[j]);
                ar[j] = fma2(h2.x, ur.x, ar[j]); ar[j] = fma2(h2.y, ur.y, ar[j]);
                ah[j] = fma2(h2.x, uh.x, ah[j]); ah[j] = fma2(h2.y, uh.y, ah[j]);
            }
        }

        const int mk = sTok[lane*(TT+1) + t];
        float hv[UW];
#pragma unroll
        for (int j = 0; j < UW; j++) {
            float vz = hsum2(az[j]), vr = hsum2(ar[j]), vh = hsum2(ah[j]);
            int lu = w*UW + j;
            float xz = sX[lane*XS + lu];
            float xr = sX[lane*XS + UT + lu];
            float xh = sX[lane*XS + 2*UT + lu];
            float z  = 1.f / (1.f + __expf(-(xz + vz + bz[j])));
            float r  = 1.f / (1.f + __expf(-(xr + vr + brr[j])));
            float hh = tanhf(xh + r * (vh + bh[j]));
            float hold = hrow[uu0 + j];
            float hnew = z*hold + (1.f - z)*hh;
            hv[j] = (mk != 0) ? hnew : hold;
        }
        if constexpr (UW == 4) {
            float4 v = make_float4(hv[0], hv[1], hv[2], hv[3]);
            *reinterpret_cast<float4*>(hn + (size_t)b*UNITS + uu0) = v;
            *reinterpret_cast<float4*>(out + ((size_t)b*TT + t)*UNITS + uu0) = v;
        } else {
            float2 v = make_float2(hv[0], hv[1]);
            *reinterpret_cast<float2*>(hn + (size_t)b*UNITS + uu0) = v;
            *reinterpret_cast<float2*>(out + ((size_t)b*TT + t)*UNITS + uu0) = v;
        }

        // group barrier (25 CTAs of this batch tile)
        __syncthreads();
        if (tid == 0) {
            unsigned* c = cnt + grp*32;
            unsigned* g = gen + grp*32;
            unsigned target = (unsigned)(t + 1);
            unsigned arr;
            asm volatile("atom.release.gpu.global.add.u32 %0, [%1], 1;"
                         : "=r"(arr) : "l"(c) : "memory");
            if (arr == (unsigned)(GROUP_CTAS - 1)) {
                asm volatile("st.relaxed.gpu.global.u32 [%0], 0;" :: "l"(c) : "memory");
                asm volatile("st.release.gpu.global.u32 [%0], %1;" :: "l"(g), "r"(target) : "memory");
            } else {
                unsigned gv;
                do {
                    asm volatile("ld.acquire.gpu.global.u32 %0, [%1];"
                                 : "=r"(gv) : "l"(g) : "memory");
                } while (gv < target);
            }
        }
        __syncthreads();
    }
}

extern "C" void kernel_launch(void* const* d_in, const int* in_sizes, int n_in,
                              void* d_out, int out_size)
{
    const int*   tokens = (const int*)  d_in[0];
    const float* emb    = (const float*)d_in[1];
    const float* gamma  = (const float*)d_in[2];
    const float* beta   = (const float*)d_in[3];
    const float* mmean  = (const float*)d_in[4];
    const float* mvar   = (const float*)d_in[5];
    const float* W1     = (const float*)d_in[6];
    const float* Ur1    = (const float*)d_in[7];
    const float* b1     = (const float*)d_in[8];
    const float* W2     = (const float*)d_in[9];
    const float* Ur2    = (const float*)d_in[10];
    const float* b2     = (const float*)d_in[11];

    float* out  = (float*)d_out;
    float* out2 = out + OUT2_OFF;
    float* out1 = out + OUT1_OFF;
    float* h2o  = out + H2_OFF;
    float* h1o  = out + H1_OFF;

    void *p_xn, *p_xw1, *p_xw2, *p_h1, *p_h2, *p_c1, *p_g1, *p_c2, *p_g2;
    cudaGetSymbolAddress(&p_xn,  g_xn);
    cudaGetSymbolAddress(&p_xw1, g_xw1);
    cudaGetSymbolAddress(&p_xw2, g_xw2);
    cudaGetSymbolAddress(&p_h1,  g_h1);
    cudaGetSymbolAddress(&p_h2,  g_h2);
    cudaGetSymbolAddress(&p_c1,  g_cnt1);
    cudaGetSymbolAddress(&p_g1,  g_gen1);
    cudaGetSymbolAddress(&p_c2,  g_cnt2);
    cudaGetSymbolAddress(&p_g2,  g_gen2);
    float* xn  = (float*)p_xn;
    float* xw1 = (float*)p_xw1;
    float* xw2 = (float*)p_xw2;
    float* h1p = (float*)p_h1;
    float* h2p = (float*)p_h2;

    // layer shapes: L1 UT=16 UW=4 -> grid(25,4), 128 thr; L2 UT=8 UW=2 -> grid(25,4), 128 thr
    constexpr int L1_SMEM = (16*3*(NU1+4) + 32*(NU1+4) + 32*(3*16+1)) * 4 + 32*(TT+1)*4;
    constexpr int L2_SMEM = (8*3*(NU2+4) + 32*(NU2+4) + 32*(3*8+1)) * 4 + 32*(TT+1)*4;

    cudaFuncSetAttribute(gru_layer<NU1, 16, 4, 25>,
                         cudaFuncAttributeMaxDynamicSharedMemorySize, L1_SMEM);
    cudaFuncSetAttribute(gru_layer<NU2, 8, 2, 25>,
                         cudaFuncAttributeMaxDynamicSharedMemorySize, L2_SMEM);

    embed_bn<<<(BB*TT*EMBD + 255)/256, 256>>>(tokens, emb, gamma, beta, mmean, mvar);
    init_state<<<(2*BB*NU1 + 255)/256, 256>>>();

    // xw1 = xn @ W1 + b1[0]
    sgemm<false><<<dim3((3*NU1 + 63)/64, (BB*TT)/64), 256>>>(xn, W1, b1, xw1, 3*NU1, EMBD);

    gru_layer<NU1, 16, 4, 25><<<dim3(NU1/16, BB/32), 128, L1_SMEM>>>(
        xw1, Ur1, b1 + 3*NU1, tokens, out1, h1p, (unsigned*)p_c1, (unsigned*)p_g1);

    copy_h<<<(BB*NU1 + 255)/256, 256>>>(h1p, h1o, BB*NU1);   // T even -> final in buf 0

    // xw2 = out1 @ W2 + b2[0] (gather rows from out1 [b][t][400])
    sgemm<true><<<dim3((3*NU2 + 63)/64, (BB*TT)/64), 256>>>(out1, W2, b2, xw2, 3*NU2, NU1);

    gru_layer<NU2, 8, 2, 25><<<dim3(NU2/8, BB/32), 128, L2_SMEM>>>(
        xw2, Ur2, b2 + 3*NU2, tokens, out2, h2p, (unsigned*)p_c2, (unsigned*)p_g2);

    copy_h<<<(BB*NU2 + 255)/256, 256>>>(h2p, h2o, BB*NU2);
}

// round 6
// speedup vs baseline: 2.6942x; 1.0275x over previous
#include <cuda_runtime.h>
#include <cstdint>
#include <cstddef>

#define BB 128
#define TT 256
#define EMBD 200
#define NU1 400
#define NU2 200

// output layout: out2 | out1 | h2 | h1
#define OUT2_OFF 0
#define OUT1_OFF (BB*TT*NU2)
#define H2_OFF   (OUT1_OFF + BB*TT*NU1)
#define H1_OFF   (H2_OFF + BB*NU2)

__device__ float g_xn [(size_t)BB*TT*EMBD];
__device__ float g_xw1[(size_t)BB*TT*3*NU1];
__device__ float g_xw2[(size_t)BB*TT*3*NU2];
__device__ float g_h1 [2*BB*NU1];
__device__ float g_h2 [2*BB*NU2];
// barrier state, padded to 128B per group
__device__ unsigned g_cnt1[4*32], g_gen1[4*32], g_cnt2[4*32], g_gen2[4*32];

__global__ void embed_bn(const int* __restrict__ tokens, const float* __restrict__ emb,
                         const float* __restrict__ gamma, const float* __restrict__ beta,
                         const float* __restrict__ mmean, const float* __restrict__ mvar)
{
    int idx = blockIdx.x * blockDim.x + threadIdx.x;
    if (idx >= BB*TT*EMBD) return;
    int d = idx % EMBD;
    int m = idx / EMBD;              // m = t*128 + b
    int b = m & (BB-1), t = m >> 7;
    int tok = tokens[b*TT + t];
    float s = gamma[d] * rsqrtf(mvar[d] + 1e-3f);
    g_xn[idx] = (emb[(size_t)tok*EMBD + d] - mmean[d]) * s + beta[d];
}

__global__ void init_state()
{
    int i = blockIdx.x * blockDim.x + threadIdx.x;
    if (i < 2*BB*NU1) g_h1[i] = 0.f;
    if (i < 2*BB*NU2) g_h2[i] = 0.f;
    if (i < 4*32) { g_cnt1[i] = 0; g_gen1[i] = 0; g_cnt2[i] = 0; g_gen2[i] = 0; }
}

__global__ void copy_h(const float* __restrict__ src, float* __restrict__ dst, int n)
{
    int i = blockIdx.x * blockDim.x + threadIdx.x;
    if (i < n) dst[i] = src[i];
}

// C[M,N] = A[M,K] @ B[K,N] + bias[N]. M mult of 64, K mult of 8, N guarded.
// GATHER: A row m -> A + ((m&127)*TT + (m>>7))*K   (reads out1 stored [b][t][K])
template<bool GATHER>
__global__ void sgemm(const float* __restrict__ A, const float* __restrict__ Bw,
                      const float* __restrict__ bias, float* __restrict__ C,
                      int N, int K)
{
    __shared__ float As[8][72];
    __shared__ float Bs[8][64];
    const int tid = threadIdx.x;          // 256
    const int row0 = blockIdx.y * 64;
    const int col0 = blockIdx.x * 64;
    const int tx = tid & 15, ty = tid >> 4;
    float acc[4][4] = {};

    for (int k0 = 0; k0 < K; k0 += 8) {
#pragma unroll
        for (int i = tid; i < 512; i += 256) {
            int kk = i & 7, m = i >> 3;
            int gm = row0 + m;
            size_t off = GATHER ? ((size_t)(gm & 127)*TT + (gm >> 7))*(size_t)K + (k0+kk)
                                : (size_t)gm*K + (k0+kk);
            As[kk][m] = A[off];
        }
#pragma unroll
        for (int i = tid; i < 512; i += 256) {
            int kk = i >> 6, n = i & 63;
            int gc = col0 + n;
            Bs[kk][n] = (gc < N) ? Bw[(size_t)(k0+kk)*N + gc] : 0.f;
        }
        __syncthreads();
#pragma unroll
        for (int kk = 0; kk < 8; kk++) {
            float4 a = *reinterpret_cast<const float4*>(&As[kk][ty*4]);
            float4 b = *reinterpret_cast<const float4*>(&Bs[kk][tx*4]);
            float av[4] = {a.x,a.y,a.z,a.w};
            float bv[4] = {b.x,b.y,b.z,b.w};
#pragma unroll
            for (int ii = 0; ii < 4; ii++)
#pragma unroll
                for (int jj = 0; jj < 4; jj++)
                    acc[ii][jj] = fmaf(av[ii], bv[jj], acc[ii][jj]);
        }
        __syncthreads();
    }
#pragma unroll
    for (int ii = 0; ii < 4; ii++) {
        size_t gr = row0 + ty*4 + ii;
#pragma unroll
        for (int jj = 0; jj < 4; jj++) {
            int gc = col0 + tx*4 + jj;
            if (gc < N) C[gr*N + gc] = acc[ii][jj] + bias[gc];
        }
    }
}

// packed f32x2 fma (sm_10x)
__device__ __forceinline__ unsigned long long fma2(unsigned long long a, unsigned long long b,
                                                   unsigned long long c)
{
    unsigned long long d;
    asm("fma.rn.f32x2 %0, %1, %2, %3;" : "=l"(d) : "l"(a), "l"(b), "l"(c));
    return d;
}
__device__ __forceinline__ float hsum2(unsigned long long a)
{
    float2 f = *reinterpret_cast<float2*>(&a);
    return f.x + f.y;
}

// ---------------- persistent GRU layer ----------------
// grid (UNITS/UT, BB/32). CTA: UT units x 32 batches. Warp = UW units x 32 batches (lane=batch).
// U slice in smem forever (broadcast loads); h exchanged via L2; barrier per batch-group.
template<int UNITS, int UT, int UW, int GROUP_CTAS>
__global__ void __launch_bounds__(32*UT/UW, 1)
gru_layer(const float* __restrict__ xw, const float* __restrict__ Ur,
          const float* __restrict__ br, const int* __restrict__ tokens,
          float* __restrict__ out, float* __restrict__ hping,
          unsigned* cnt, unsigned* gen)
{
    constexpr int NTHR = 32*UT/UW;
    constexpr int KP = UNITS + 4;       // lane stride mod 32 banks -> conflict-free LDS.128
    constexpr int XS = 3*UT + 1;
    extern __shared__ float sm[];
    float* sU   = sm;                   // [UT*3][KP], row (lu*3+g)
    float* sH   = sU + UT*3*KP;         // [32][KP]
    float* sX   = sH + 32*KP;           // [32][XS]
    int*   sTok = (int*)(sX + 32*XS);   // [32][TT+1]

    const int tid  = threadIdx.x;
    const int w    = tid >> 5;
    const int lane = tid & 31;
    const int u0   = blockIdx.x * UT;
    const int b0   = blockIdx.y * 32;
    const int grp  = blockIdx.y;
    const int b    = b0 + lane;
    const int uu0  = u0 + w*UW;         // first global unit of this thread

    // one-time: U slice -> smem, transposed to [unit][gate][k]
    for (int i = tid; i < 3*UT*UNITS; i += NTHR) {
        int k = i / (3*UT), c = i % (3*UT);
        int g = c / UT, lu = c % UT;
        sU[(lu*3 + g)*KP + k] = Ur[(size_t)k*(3*UNITS) + g*UNITS + u0 + lu];
    }
    // one-time: tokens for this batch tile
    for (int i = tid; i < 32*TT; i += NTHR) {
        int bb = i / TT, tt = i % TT;
        sTok[bb*(TT+1) + tt] = tokens[(b0 + bb)*TT + tt];
    }
    // per-thread constant biases
    float bz[UW], brr[UW], bh[UW];
#pragma unroll
    for (int j = 0; j < UW; j++) {
        bz[j]  = br[uu0 + j];
        brr[j] = br[UNITS + uu0 + j];
        bh[j]  = br[2*UNITS + uu0 + j];
    }

    const float* hrow = sH + lane*KP;

    for (int t = 0; t < TT; t++) {
        const float* hg = hping + (t & 1) * (BB*UNITS);
        float*       hn = hping + ((t + 1) & 1) * (BB*UNITS);

        // stage xw tile [32][3*UT] (coalesced 64B segments)
        for (int i = tid; i < 32*3*UT; i += NTHR) {
            int bb = i / (3*UT), c = i % (3*UT);
            int g = c / UT, lu = c % UT;
            sX[bb*XS + c] = __ldg(xw + ((size_t)t*BB + b0 + bb)*(size_t)(3*UNITS)
                                      + (size_t)g*UNITS + u0 + lu);
        }
        // stage h tile [32][UNITS] from L2 (vectorized)
        for (int i = tid; i < 32*(UNITS/4); i += NTHR) {
            int bb = i / (UNITS/4), kk = i % (UNITS/4);
            float4 v = __ldcg(reinterpret_cast<const float4*>(hg + (size_t)(b0+bb)*UNITS) + kk);
            *reinterpret_cast<float4*>(&sH[bb*KP + kk*4]) = v;
        }
        __syncthreads();

        unsigned long long az[UW] = {}, ar[UW] = {}, ah[UW] = {};
#pragma unroll 4
        for (int k = 0; k < UNITS; k += 4) {
            ulonglong2 h2 = *reinterpret_cast<const ulonglong2*>(hrow + k);
#pragma unroll
            for (int j = 0; j < UW; j++) {
                const float* ub = sU + ((w*UW + j)*3)*KP + k;
                ulonglong2 uz = *reinterpret_cast<const ulonglong2*>(ub);
                ulonglong2 ur = *reinterpret_cast<const ulonglong2*>(ub + KP);
                ulonglong2 uh = *reinterpret_cast<const ulonglong2*>(ub + 2*KP);
                az[j] = fma2(h2.x, uz.x, az[j]); az[j] = fma2(h2.y, uz.y, az[j]);
                ar[j] = fma2(h2.x, ur.x, ar[j]); ar[j] = fma2(h2.y, ur.y, ar[j]);
                ah[j] = fma2(h2.x, uh.x, ah[j]); ah[j] = fma2(h2.y, uh.y, ah[j]);
            }
        }

        const int mk = sTok[lane*(TT+1) + t];
        float hv[UW];
#pragma unroll
        for (int j = 0; j < UW; j++) {
            float vz = hsum2(az[j]), vr = hsum2(ar[j]), vh = hsum2(ah[j]);
            int lu = w*UW + j;
            float xz = sX[lane*XS + lu];
            float xr = sX[lane*XS + UT + lu];
            float xh = sX[lane*XS + 2*UT + lu];
            float z  = 1.f / (1.f + __expf(-(xz + vz + bz[j])));
            float r  = 1.f / (1.f + __expf(-(xr + vr + brr[j])));
            float hh = tanhf(xh + r * (vh + bh[j]));
            float hold = hrow[uu0 + j];
            float hnew = z*hold + (1.f - z)*hh;
            hv[j] = (mk != 0) ? hnew : hold;
        }
        if constexpr (UW == 4) {
            float4 v = make_float4(hv[0], hv[1], hv[2], hv[3]);
            *reinterpret_cast<float4*>(hn + (size_t)b*UNITS + uu0) = v;
            *reinterpret_cast<float4*>(out + ((size_t)b*TT + t)*UNITS + uu0) = v;
        } else if constexpr (UW == 2) {
            float2 v = make_float2(hv[0], hv[1]);
            *reinterpret_cast<float2*>(hn + (size_t)b*UNITS + uu0) = v;
            *reinterpret_cast<float2*>(out + ((size_t)b*TT + t)*UNITS + uu0) = v;
        } else {
            hn[(size_t)b*UNITS + uu0] = hv[0];
            out[((size_t)b*TT + t)*UNITS + uu0] = hv[0];
        }

        // group barrier (GROUP_CTAS CTAs of this batch tile)
        __syncthreads();
        if (tid == 0) {
            unsigned* c = cnt + grp*32;
            unsigned* g = gen + grp*32;
            unsigned target = (unsigned)(t + 1);
            unsigned arr;
            asm volatile("atom.release.gpu.global.add.u32 %0, [%1], 1;"
                         : "=r"(arr) : "l"(c) : "memory");
            if (arr == (unsigned)(GROUP_CTAS - 1)) {
                asm volatile("st.relaxed.gpu.global.u32 [%0], 0;" :: "l"(c) : "memory");
                asm volatile("st.release.gpu.global.u32 [%0], %1;" :: "l"(g), "r"(target) : "memory");
            } else {
                unsigned gv;
                do {
                    asm volatile("ld.acquire.gpu.global.u32 %0, [%1];"
                                 : "=r"(gv) : "l"(g) : "memory");
                } while (gv < target);
            }
        }
        __syncthreads();
    }
}

extern "C" void kernel_launch(void* const* d_in, const int* in_sizes, int n_in,
                              void* d_out, int out_size)
{
    const int*   tokens = (const int*)  d_in[0];
    const float* emb    = (const float*)d_in[1];
    const float* gamma  = (const float*)d_in[2];
    const float* beta   = (const float*)d_in[3];
    const float* mmean  = (const float*)d_in[4];
    const float* mvar   = (const float*)d_in[5];
    const float* W1     = (const float*)d_in[6];
    const float* Ur1    = (const float*)d_in[7];
    const float* b1     = (const float*)d_in[8];
    const float* W2     = (const float*)d_in[9];
    const float* Ur2    = (const float*)d_in[10];
    const float* b2     = (const float*)d_in[11];

    float* out  = (float*)d_out;
    float* out2 = out + OUT2_OFF;
    float* out1 = out + OUT1_OFF;
    float* h2o  = out + H2_OFF;
    float* h1o  = out + H1_OFF;

    void *p_xn, *p_xw1, *p_xw2, *p_h1, *p_h2, *p_c1, *p_g1, *p_c2, *p_g2;
    cudaGetSymbolAddress(&p_xn,  g_xn);
    cudaGetSymbolAddress(&p_xw1, g_xw1);
    cudaGetSymbolAddress(&p_xw2, g_xw2);
    cudaGetSymbolAddress(&p_h1,  g_h1);
    cudaGetSymbolAddress(&p_h2,  g_h2);
    cudaGetSymbolAddress(&p_c1,  g_cnt1);
    cudaGetSymbolAddress(&p_g1,  g_gen1);
    cudaGetSymbolAddress(&p_c2,  g_cnt2);
    cudaGetSymbolAddress(&p_g2,  g_gen2);
    float* xn  = (float*)p_xn;
    float* xw1 = (float*)p_xw1;
    float* xw2 = (float*)p_xw2;
    float* h1p = (float*)p_h1;
    float* h2p = (float*)p_h2;

    // L1: UT=16 UW=2 -> 256 thr (8 warps), grid(25,4); L2: UT=8 UW=1 -> 256 thr, grid(25,4)
    constexpr int L1_SMEM = (16*3*(NU1+4) + 32*(NU1+4) + 32*(3*16+1)) * 4 + 32*(TT+1)*4;
    constexpr int L2_SMEM = (8*3*(NU2+4) + 32*(NU2+4) + 32*(3*8+1)) * 4 + 32*(TT+1)*4;

    cudaFuncSetAttribute(gru_layer<NU1, 16, 2, 25>,
                         cudaFuncAttributeMaxDynamicSharedMemorySize, L1_SMEM);
    cudaFuncSetAttribute(gru_layer<NU2, 8, 1, 25>,
                         cudaFuncAttributeMaxDynamicSharedMemorySize, L2_SMEM);

    embed_bn<<<(BB*TT*EMBD + 255)/256, 256>>>(tokens, emb, gamma, beta, mmean, mvar);
    init_state<<<(2*BB*NU1 + 255)/256, 256>>>();

    // xw1 = xn @ W1 + b1[0]
    sgemm<false><<<dim3((3*NU1 + 63)/64, (BB*TT)/64), 256>>>(xn, W1, b1, xw1, 3*NU1, EMBD);

    gru_layer<NU1, 16, 2, 25><<<dim3(NU1/16, BB/32), 256, L1_SMEM>>>(
        xw1, Ur1, b1 + 3*NU1, tokens, out1, h1p, (unsigned*)p_c1, (unsigned*)p_g1);

    copy_h<<<(BB*NU1 + 255)/256, 256>>>(h1p, h1o, BB*NU1);   // T even -> final in buf 0

    // xw2 = out1 @ W2 + b2[0] (gather rows from out1 [b][t][400])
    sgemm<true><<<dim3((3*NU2 + 63)/64, (BB*TT)/64), 256>>>(out1, W2, b2, xw2, 3*NU2, NU1);

    gru_layer<NU2, 8, 1, 25><<<dim3(NU2/8, BB/32), 256, L2_SMEM>>>(
        xw2, Ur2, b2 + 3*NU2, tokens, out2, h2p, (unsigned*)p_c2, (unsigned*)p_g2);

    copy_h<<<(BB*NU2 + 255)/256, 256>>>(h2p, h2o, BB*NU2);
}

// round 7
// speedup vs baseline: 3.5357x; 1.3124x over previous
#include <cuda_runtime.h>
#include <cstdint>
#include <cstddef>

#define BB 128
#define TT 256
#define EMBD 200
#define NU1 400
#define NU2 200

// output layout: out2 | out1 | h2 | h1
#define OUT2_OFF 0
#define OUT1_OFF (BB*TT*NU2)
#define H2_OFF   (OUT1_OFF + BB*TT*NU1)
#define H1_OFF   (H2_OFF + BB*NU2)

__device__ float g_xn [(size_t)BB*TT*EMBD];
__device__ float g_xw1[(size_t)BB*TT*3*NU1];
__device__ float g_xw2[(size_t)BB*TT*3*NU2];
__device__ float g_h1 [2*BB*NU1];
__device__ float g_h2 [2*BB*NU2];
// barrier state, padded: one 128B-spaced slot per batch-group
__device__ unsigned g_cnt1[4*32], g_gen1[4*32], g_cnt2[4*32], g_gen2[4*32];

// ---- cp.async helpers ----
__device__ __forceinline__ void cp_async4(uint32_t s, const void* g)
{
    asm volatile("cp.async.ca.shared.global [%0], [%1], 4;" :: "r"(s), "l"(g));
}
__device__ __forceinline__ void cp_async16(uint32_t s, const void* g)
{
    asm volatile("cp.async.cg.shared.global [%0], [%1], 16;" :: "r"(s), "l"(g));
}
__device__ __forceinline__ void cp_commit() { asm volatile("cp.async.commit_group;"); }
__device__ __forceinline__ void cp_wait0()  { asm volatile("cp.async.wait_all;"); }

__global__ void embed_bn(const int* __restrict__ tokens, const float* __restrict__ emb,
                         const float* __restrict__ gamma, const float* __restrict__ beta,
                         const float* __restrict__ mmean, const float* __restrict__ mvar)
{
    int idx = blockIdx.x * blockDim.x + threadIdx.x;
    if (idx >= BB*TT*EMBD) return;
    int d = idx % EMBD;
    int m = idx / EMBD;              // m = t*128 + b
    int b = m & (BB-1), t = m >> 7;
    int tok = tokens[b*TT + t];
    float s = gamma[d] * rsqrtf(mvar[d] + 1e-3f);
    g_xn[idx] = (emb[(size_t)tok*EMBD + d] - mmean[d]) * s + beta[d];
}

__global__ void init_state()
{
    int i = blockIdx.x * blockDim.x + threadIdx.x;
    if (i < 2*BB*NU1) g_h1[i] = 0.f;
    if (i < 2*BB*NU2) g_h2[i] = 0.f;
    if (i < 4*32) { g_cnt1[i] = 0; g_gen1[i] = 0; g_cnt2[i] = 0; g_gen2[i] = 0; }
}

__global__ void copy_h(const float* __restrict__ src, float* __restrict__ dst, int n)
{
    int i = blockIdx.x * blockDim.x + threadIdx.x;
    if (i < n) dst[i] = src[i];
}

// C[M,N] = A[M,K] @ B[K,N] + bias[N]. M mult of 64, K mult of 8, N guarded.
// Register double-buffered: gmem loads of chunk k+1 overlap FMAs of chunk k.
// GATHER: A row m -> A + ((m&127)*TT + (m>>7))*K   (reads out1 stored [b][t][K])
template<bool GATHER>
__global__ void sgemm(const float* __restrict__ A, const float* __restrict__ Bw,
                      const float* __restrict__ bias, float* __restrict__ C,
                      int N, int K)
{
    __shared__ float As[8][72];
    __shared__ float Bs[8][64];
    const int tid = threadIdx.x;          // 256
    const int row0 = blockIdx.y * 64;
    const int col0 = blockIdx.x * 64;
    const int tx = tid & 15, ty = tid >> 4;
    float acc[4][4] = {};

    // per-thread load slots: A items i=tid, tid+256; B items i=tid, tid+256
    float ra[2], rb[2];
    auto loadA = [&](int k0, int s) -> float {
        int i = tid + s*256;
        int kk = i & 7, m = i >> 3;
        int gm = row0 + m;
        size_t off = GATHER ? ((size_t)(gm & 127)*TT + (gm >> 7))*(size_t)K + (k0+kk)
                            : (size_t)gm*K + (k0+kk);
        return A[off];
    };
    auto loadB = [&](int k0, int s) -> float {
        int i = tid + s*256;
        int kk = i >> 6, n = i & 63;
        int gc = col0 + n;
        return (gc < N) ? Bw[(size_t)(k0+kk)*N + gc] : 0.f;
    };

    ra[0] = loadA(0,0); ra[1] = loadA(0,1);
    rb[0] = loadB(0,0); rb[1] = loadB(0,1);

    for (int k0 = 0; k0 < K; k0 += 8) {
#pragma unroll
        for (int s = 0; s < 2; s++) {
            int i = tid + s*256;
            As[i & 7][i >> 3] = ra[s];
            Bs[i >> 6][i & 63] = rb[s];
        }
        __syncthreads();
        if (k0 + 8 < K) {
            ra[0] = loadA(k0+8,0); ra[1] = loadA(k0+8,1);
            rb[0] = loadB(k0+8,0); rb[1] = loadB(k0+8,1);
        }
#pragma unroll
        for (int kk = 0; kk < 8; kk++) {
            float4 a = *reinterpret_cast<const float4*>(&As[kk][ty*4]);
            float4 b = *reinterpret_cast<const float4*>(&Bs[kk][tx*4]);
            float av[4] = {a.x,a.y,a.z,a.w};
            float bv[4] = {b.x,b.y,b.z,b.w};
#pragma unroll
            for (int ii = 0; ii < 4; ii++)
#pragma unroll
                for (int jj = 0; jj < 4; jj++)
                    acc[ii][jj] = fmaf(av[ii], bv[jj], acc[ii][jj]);
        }
        __syncthreads();
    }
#pragma unroll
    for (int ii = 0; ii < 4; ii++) {
        size_t gr = row0 + ty*4 + ii;
#pragma unroll
        for (int jj = 0; jj < 4; jj++) {
            int gc = col0 + tx*4 + jj;
            if (gc < N) C[gr*N + gc] = acc[ii][jj] + bias[gc];
        }
    }
}

// packed f32x2 fma (sm_10x)
__device__ __forceinline__ unsigned long long fma2(unsigned long long a, unsigned long long b,
                                                   unsigned long long c)
{
    unsigned long long d;
    asm("fma.rn.f32x2 %0, %1, %2, %3;" : "=l"(d) : "l"(a), "l"(b), "l"(c));
    return d;
}
__device__ __forceinline__ float hsum2(unsigned long long a)
{
    float2 f = *reinterpret_cast<float2*>(&a);
    return f.x + f.y;
}

// ---------------- persistent GRU layer ----------------
// grid (UNITS/UT, BB/32). CTA: UT units x 32 batches. Warp = UW units x 32 batches (lane=batch).
// U slice smem-resident; xw(t+1) prefetched via cp.async ACROSS the grid barrier;
// h staged via cp.async.cg post-barrier; token mask bit-packed.
template<int UNITS, int UT, int UW, int GROUP_CTAS>
__global__ void __launch_bounds__(32*UT/UW, 1)
gru_layer(const float* __restrict__ xw, const float* __restrict__ Ur,
          const float* __restrict__ br, const int* __restrict__ tokens,
          float* __restrict__ out, float* __restrict__ hping,
          unsigned* cnt, unsigned* gen)
{
    constexpr int NTHR = 32*UT/UW;
    constexpr int KP = UNITS + 4;       // lane stride -> conflict-free LDS.128
    constexpr int XS = 3*UT;
    extern __shared__ float sm[];
    float*    sU    = sm;                    // [UT*3][KP], row (lu*3+g)
    float*    sH    = sU + UT*3*KP;          // [32][KP]
    float*    sX    = sH + 32*KP;            // [2][32][XS]
    unsigned* sMask = (unsigned*)(sX + 2*32*XS);  // [32][8] bit t of word t>>5

    const int tid  = threadIdx.x;
    const int w    = tid >> 5;
    const int lane = tid & 31;
    const int u0   = blockIdx.x * UT;
    const int b0   = blockIdx.y * 32;
    const int grp  = blockIdx.y;
    const int b    = b0 + lane;
    const int uu0  = u0 + w*UW;

    // one-time: U slice -> smem, transposed to [unit][gate][k]
    for (int i = tid; i < 3*UT*UNITS; i += NTHR) {
        int k = i / (3*UT), c = i % (3*UT);
        int g = c / UT, lu = c % UT;
        sU[(lu*3 + g)*KP + k] = Ur[(size_t)k*(3*UNITS) + g*UNITS + u0 + lu];
    }
    // one-time: bit-packed mask
    for (int i = tid; i < 32*8; i += NTHR) {
        int bb = i >> 3, wd = i & 7;
        unsigned m = 0;
        for (int j = 0; j < 32; j++)
            m |= (tokens[(b0 + bb)*TT + wd*32 + j] != 0 ? 1u : 0u) << j;
        sMask[bb*8 + wd] = m;
    }
    // stage sX[0] for t=0
    {
        uint32_t sx0 = (uint32_t)__cvta_generic_to_shared(sX);
        for (int i = tid; i < 32*XS; i += NTHR) {
            int bb = i / XS, c = i % XS;
            int g = c / UT, lu = c % UT;
            cp_async4(sx0 + (uint32_t)i*4,
                      xw + ((size_t)0*BB + b0 + bb)*(size_t)(3*UNITS) + (size_t)g*UNITS + u0 + lu);
        }
        cp_commit();
    }

    float bz[UW], brr[UW], bh[UW];
#pragma unroll
    for (int j = 0; j < UW; j++) {
        bz[j]  = br[uu0 + j];
        brr[j] = br[UNITS + uu0 + j];
        bh[j]  = br[2*UNITS + uu0 + j];
    }

    const float* hrow = sH + lane*KP;
    const uint32_t sH_s = (uint32_t)__cvta_generic_to_shared(sH);
    const uint32_t sX_s = (uint32_t)__cvta_generic_to_shared(sX);

    for (int t = 0; t < TT; t++) {
        const float* hg = hping + (t & 1) * (BB*UNITS);
        float*       hn = hping + ((t + 1) & 1) * (BB*UNITS);
        const float* sXc = sX + (t & 1)*32*XS;

        // stage h tile [32][UNITS] from L2 (cp.async.cg 16B, full MLP)
        for (int i = tid; i < 32*(UNITS/4); i += NTHR) {
            int bb = i / (UNITS/4), kk = i % (UNITS/4);
            cp_async16(sH_s + (uint32_t)(bb*KP + kk*4)*4,
                       hg + (size_t)(b0+bb)*UNITS + kk*4);
        }
        cp_commit();
        cp_wait0();
        __syncthreads();

        unsigned long long az[UW] = {}, ar[UW] = {}, ah[UW] = {};
#pragma unroll 4
        for (int k = 0; k < UNITS; k += 4) {
            ulonglong2 h2 = *reinterpret_cast<const ulonglong2*>(hrow + k);
#pragma unroll
            for (int j = 0; j < UW; j++) {
                const float* ub = sU + ((w*UW + j)*3)*KP + k;
                ulonglong2 uz = *reinterpret_cast<const ulonglong2*>(ub);
                ulonglong2 ur = *reinterpret_cast<const ulonglong2*>(ub + KP);
                ulonglong2 uh = *reinterpret_cast<const ulonglong2*>(ub + 2*KP);
                az[j] = fma2(h2.x, uz.x, az[j]); az[j] = fma2(h2.y, uz.y, az[j]);
                ar[j] = fma2(h2.x, ur.x, ar[j]); ar[j] = fma2(h2.y, ur.y, ar[j]);
                ah[j] = fma2(h2.x, uh.x, ah[j]); ah[j] = fma2(h2.y, uh.y, ah[j]);
            }
        }

        const int mk = (sMask[lane*8 + (t >> 5)] >> (t & 31)) & 1;
        float hv[UW];
#pragma unroll
        for (int j = 0; j < UW; j++) {
            float vz = hsum2(az[j]), vr = hsum2(ar[j]), vh = hsum2(ah[j]);
            int lu = w*UW + j;
            float xz = sXc[lane*XS + lu];
            float xr = sXc[lane*XS + UT + lu];
            float xh = sXc[lane*XS + 2*UT + lu];
            float z  = 1.f / (1.f + __expf(-(xz + vz + bz[j])));
            float r  = 1.f / (1.f + __expf(-(xr + vr + brr[j])));
            float hh = tanhf(xh + r * (vh + bh[j]));
            float hold = hrow[uu0 + j];
            float hnew = z*hold + (1.f - z)*hh;
            hv[j] = mk ? hnew : hold;
        }
        if constexpr (UW == 2) {
            float2 v = make_float2(hv[0], hv[1]);
            *reinterpret_cast<float2*>(hn + (size_t)b*UNITS + uu0) = v;
            *reinterpret_cast<float2*>(out + ((size_t)b*TT + t)*UNITS + uu0) = v;
        } else {
            hn[(size_t)b*UNITS + uu0] = hv[0];
            out[((size_t)b*TT + t)*UNITS + uu0] = hv[0];
        }

        // prefetch xw for t+1 ACROSS the barrier (cp.async, waited next iter)
        if (t + 1 < TT) {
            uint32_t dst = sX_s + (uint32_t)(((t+1) & 1)*32*XS)*4;
            for (int i = tid; i < 32*XS; i += NTHR) {
                int bb = i / XS, c = i % XS;
                int g = c / UT, lu = c % UT;
                cp_async4(dst + (uint32_t)i*4,
                          xw + ((size_t)(t+1)*BB + b0 + bb)*(size_t)(3*UNITS)
                             + (size_t)g*UNITS + u0 + lu);
            }
            cp_commit();
        }

        // group barrier (GROUP_CTAS CTAs of this batch tile)
        __syncthreads();
        if (tid == 0) {
            unsigned* c = cnt + grp*32;
            unsigned* g = gen + grp*32;
            unsigned target = (unsigned)(t + 1);
            unsigned arr;
            asm volatile("atom.release.gpu.global.add.u32 %0, [%1], 1;"
                         : "=r"(arr) : "l"(c) : "memory");
            if (arr == (unsigned)(GROUP_CTAS - 1)) {
                asm volatile("st.relaxed.gpu.global.u32 [%0], 0;" :: "l"(c) : "memory");
                asm volatile("st.release.gpu.global.u32 [%0], %1;" :: "l"(g), "r"(target) : "memory");
            } else {
                unsigned gv;
                do {
                    asm volatile("ld.acquire.gpu.global.u32 %0, [%1];"
                                 : "=r"(gv) : "l"(g) : "memory");
                } while (gv < target);
            }
        }
        __syncthreads();
    }
}

extern "C" void kernel_launch(void* const* d_in, const int* in_sizes, int n_in,
                              void* d_out, int out_size)
{
    const int*   tokens = (const int*)  d_in[0];
    const float* emb    = (const float*)d_in[1];
    const float* gamma  = (const float*)d_in[2];
    const float* beta   = (const float*)d_in[3];
    const float* mmean  = (const float*)d_in[4];
    const float* mvar   = (const float*)d_in[5];
    const float* W1     = (const float*)d_in[6];
    const float* Ur1    = (const float*)d_in[7];
    const float* b1     = (const float*)d_in[8];
    const float* W2     = (const float*)d_in[9];
    const float* Ur2    = (const float*)d_in[10];
    const float* b2     = (const float*)d_in[11];

    float* out  = (float*)d_out;
    float* out2 = out + OUT2_OFF;
    float* out1 = out + OUT1_OFF;
    float* h2o  = out + H2_OFF;
    float* h1o  = out + H1_OFF;

    void *p_xn, *p_xw1, *p_xw2, *p_h1, *p_h2, *p_c1, *p_g1, *p_c2, *p_g2;
    cudaGetSymbolAddress(&p_xn,  g_xn);
    cudaGetSymbolAddress(&p_xw1, g_xw1);
    cudaGetSymbolAddress(&p_xw2, g_xw2);
    cudaGetSymbolAddress(&p_h1,  g_h1);
    cudaGetSymbolAddress(&p_h2,  g_h2);
    cudaGetSymbolAddress(&p_c1,  g_cnt1);
    cudaGetSymbolAddress(&p_g1,  g_gen1);
    cudaGetSymbolAddress(&p_c2,  g_cnt2);
    cudaGetSymbolAddress(&p_g2,  g_gen2);
    float* xn  = (float*)p_xn;
    float* xw1 = (float*)p_xw1;
    float* xw2 = (float*)p_xw2;
    float* h1p = (float*)p_h1;
    float* h2p = (float*)p_h2;

    // smem sizes (floats): sU + sH + 2*sX, plus mask bytes
    constexpr int L1_SMEM = (16*3*(NU1+4) + 32*(NU1+4) + 2*32*48) * 4 + 32*8*4;
    constexpr int L2_SMEM = (8*3*(NU2+4) + 32*(NU2+4) + 2*32*24) * 4 + 32*8*4;

    cudaFuncSetAttribute(gru_layer<NU1, 16, 2, 25>,
                         cudaFuncAttributeMaxDynamicSharedMemorySize, L1_SMEM);
    cudaFuncSetAttribute(gru_layer<NU2, 8, 1, 25>,
                         cudaFuncAttributeMaxDynamicSharedMemorySize, L2_SMEM);

    embed_bn<<<(BB*TT*EMBD + 255)/256, 256>>>(tokens, emb, gamma, beta, mmean, mvar);
    init_state<<<(2*BB*NU1 + 255)/256, 256>>>();

    // xw1 = xn @ W1 + b1[0]
    sgemm<false><<<dim3((3*NU1 + 63)/64, (BB*TT)/64), 256>>>(xn, W1, b1, xw1, 3*NU1, EMBD);

    gru_layer<NU1, 16, 2, 25><<<dim3(NU1/16, BB/32), 256, L1_SMEM>>>(
        xw1, Ur1, b1 + 3*NU1, tokens, out1, h1p, (unsigned*)p_c1, (unsigned*)p_g1);

    copy_h<<<(BB*NU1 + 255)/256, 256>>>(h1p, h1o, BB*NU1);   // T even -> final in buf 0

    // xw2 = out1 @ W2 + b2[0] (gather rows from out1 [b][t][400])
    sgemm<true><<<dim3((3*NU2 + 63)/64, (BB*TT)/64), 256>>>(out1, W2, b2, xw2, 3*NU2, NU1);

    gru_layer<NU2, 8, 1, 25><<<dim3(NU2/8, BB/32), 256, L2_SMEM>>>(
        xw2, Ur2, b2 + 3*NU2, tokens, out2, h2p, (unsigned*)p_c2, (unsigned*)p_g2);

    copy_h<<<(BB*NU2 + 255)/256, 256>>>(h2p, h2o, BB*NU2);
}

// round 8
// speedup vs baseline: 3.5488x; 1.0037x over previous
#include <cuda_runtime.h>
#include <cstdint>
#include <cstddef>

#define BB 128
#define TT 256
#define EMBD 200
#define NU1 400
#define NU2 200

// output layout: out2 | out1 | h2 | h1
#define OUT2_OFF 0
#define OUT1_OFF (BB*TT*NU2)
#define H2_OFF   (OUT1_OFF + BB*TT*NU1)
#define H1_OFF   (H2_OFF + BB*NU2)

__device__ float g_xn [(size_t)BB*TT*EMBD];
__device__ float g_xw1[(size_t)BB*TT*3*NU1];
__device__ float g_xw2[(size_t)BB*TT*3*NU2];
__device__ float g_h1 [2*BB*NU1];
__device__ float g_h2 [2*BB*NU2];
// barrier state, padded: one 128B-spaced slot per batch-group
__device__ unsigned g_cnt1[4*32], g_gen1[4*32], g_cnt2[4*32], g_gen2[4*32];

// ---- cp.async helpers ----
__device__ __forceinline__ void cp_async4(uint32_t s, const void* g)
{
    asm volatile("cp.async.ca.shared.global [%0], [%1], 4;" :: "r"(s), "l"(g));
}
__device__ __forceinline__ void cp_async16(uint32_t s, const void* g)
{
    asm volatile("cp.async.cg.shared.global [%0], [%1], 16;" :: "r"(s), "l"(g));
}
__device__ __forceinline__ void cp_commit() { asm volatile("cp.async.commit_group;"); }
__device__ __forceinline__ void cp_wait0()  { asm volatile("cp.async.wait_all;"); }

// packed f32x2 ops (sm_10x)
__device__ __forceinline__ unsigned long long fma2(unsigned long long a, unsigned long long b,
                                                   unsigned long long c)
{
    unsigned long long d;
    asm("fma.rn.f32x2 %0, %1, %2, %3;" : "=l"(d) : "l"(a), "l"(b), "l"(c));
    return d;
}
__device__ __forceinline__ unsigned long long pack2(float lo, float hi)
{
    unsigned long long d;
    asm("mov.b64 %0, {%1, %2};" : "=l"(d) : "f"(lo), "f"(hi));
    return d;
}
__device__ __forceinline__ float hsum2(unsigned long long a)
{
    float2 f = *reinterpret_cast<float2*>(&a);
    return f.x + f.y;
}
__device__ __forceinline__ float2 unpack2(unsigned long long a)
{
    return *reinterpret_cast<float2*>(&a);
}

__global__ void embed_bn(const int* __restrict__ tokens, const float* __restrict__ emb,
                         const float* __restrict__ gamma, const float* __restrict__ beta,
                         const float* __restrict__ mmean, const float* __restrict__ mvar)
{
    int idx = blockIdx.x * blockDim.x + threadIdx.x;
    if (idx >= BB*TT*EMBD) return;
    int d = idx % EMBD;
    int m = idx / EMBD;              // m = t*128 + b
    int b = m & (BB-1), t = m >> 7;
    int tok = tokens[b*TT + t];
    float s = gamma[d] * rsqrtf(mvar[d] + 1e-3f);
    g_xn[idx] = (emb[(size_t)tok*EMBD + d] - mmean[d]) * s + beta[d];
}

__global__ void init_state()
{
    int i = blockIdx.x * blockDim.x + threadIdx.x;
    if (i < 2*BB*NU1) g_h1[i] = 0.f;
    if (i < 2*BB*NU2) g_h2[i] = 0.f;
    if (i < 4*32) { g_cnt1[i] = 0; g_gen1[i] = 0; g_cnt2[i] = 0; g_gen2[i] = 0; }
}

__global__ void copy_h(const float* __restrict__ src, float* __restrict__ dst, int n)
{
    int i = blockIdx.x * blockDim.x + threadIdx.x;
    if (i < n) dst[i] = src[i];
}

// C[M,N] = A[M,K] @ B[K,N] + bias[N], f32x2-packed inner loop.
// M mult of 64, K mult of 8, N guarded.
// GATHER: A row m -> A + ((m&127)*TT + (m>>7))*K   (reads out1 stored [b][t][K])
template<bool GATHER>
__global__ void __launch_bounds__(256)
sgemm(const float* __restrict__ A, const float* __restrict__ Bw,
      const float* __restrict__ bias, float* __restrict__ C,
      int N, int K)
{
    __shared__ float As[8][72];
    __shared__ float Bs[8][64];
    const int tid = threadIdx.x;          // 256
    const int row0 = blockIdx.y * 64;
    const int col0 = blockIdx.x * 64;
    const int tx = tid & 15, ty = tid >> 4;

    // acc2[mp][n]: packed pair (m = ty*4+mp*2, ty*4+mp*2+1) x column (tx*4+n)
    unsigned long long acc2[2][4] = {};

    float ra[2], rb[2];
    auto loadA = [&](int k0, int s) -> float {
        int i = tid + s*256;
        int kk = i & 7, m = i >> 3;
        int gm = row0 + m;
        size_t off = GATHER ? ((size_t)(gm & 127)*TT + (gm >> 7))*(size_t)K + (k0+kk)
                            : (size_t)gm*K + (k0+kk);
        return A[off];
    };
    auto loadB = [&](int k0, int s) -> float {
        int i = tid + s*256;
        int kk = i >> 6, n = i & 63;
        int gc = col0 + n;
        return (gc < N) ? Bw[(size_t)(k0+kk)*N + gc] : 0.f;
    };

    ra[0] = loadA(0,0); ra[1] = loadA(0,1);
    rb[0] = loadB(0,0); rb[1] = loadB(0,1);

    for (int k0 = 0; k0 < K; k0 += 8) {
#pragma unroll
        for (int s = 0; s < 2; s++) {
            int i = tid + s*256;
            As[i & 7][i >> 3] = ra[s];
            Bs[i >> 6][i & 63] = rb[s];
        }
        __syncthreads();
        if (k0 + 8 < K) {
            ra[0] = loadA(k0+8,0); ra[1] = loadA(k0+8,1);
            rb[0] = loadB(k0+8,0); rb[1] = loadB(k0+8,1);
        }
#pragma unroll
        for (int kk = 0; kk < 8; kk++) {
            ulonglong2 ap = *reinterpret_cast<const ulonglong2*>(&As[kk][ty*4]);
            float4 b = *reinterpret_cast<const float4*>(&Bs[kk][tx*4]);
            unsigned long long db0 = pack2(b.x, b.x);
            unsigned long long db1 = pack2(b.y, b.y);
            unsigned long long db2 = pack2(b.z, b.z);
            unsigned long long db3 = pack2(b.w, b.w);
            acc2[0][0] = fma2(ap.x, db0, acc2[0][0]);
            acc2[0][1] = fma2(ap.x, db1, acc2[0][1]);
            acc2[0][2] = fma2(ap.x, db2, acc2[0][2]);
            acc2[0][3] = fma2(ap.x, db3, acc2[0][3]);
            acc2[1][0] = fma2(ap.y, db0, acc2[1][0]);
            acc2[1][1] = fma2(ap.y, db1, acc2[1][1]);
            acc2[1][2] = fma2(ap.y, db2, acc2[1][2]);
            acc2[1][3] = fma2(ap.y, db3, acc2[1][3]);
        }
        __syncthreads();
    }
#pragma unroll
    for (int mp = 0; mp < 2; mp++) {
#pragma unroll
        for (int n = 0; n < 4; n++) {
            float2 v = unpack2(acc2[mp][n]);
            int gc = col0 + tx*4 + n;
            if (gc < N) {
                float bv = bias[gc];
                size_t gr0 = row0 + ty*4 + mp*2;
                C[gr0*N + gc]     = v.x + bv;
                C[(gr0+1)*N + gc] = v.y + bv;
            }
        }
    }
}

// ---------------- persistent GRU layer (unchanged from R7) ----------------
template<int UNITS, int UT, int UW, int GROUP_CTAS>
__global__ void __launch_bounds__(32*UT/UW, 1)
gru_layer(const float* __restrict__ xw, const float* __restrict__ Ur,
          const float* __restrict__ br, const int* __restrict__ tokens,
          float* __restrict__ out, float* __restrict__ hping,
          unsigned* cnt, unsigned* gen)
{
    constexpr int NTHR = 32*UT/UW;
    constexpr int KP = UNITS + 4;
    constexpr int XS = 3*UT;
    extern __shared__ float sm[];
    float*    sU    = sm;
    float*    sH    = sU + UT*3*KP;
    float*    sX    = sH + 32*KP;
    unsigned* sMask = (unsigned*)(sX + 2*32*XS);

    const int tid  = threadIdx.x;
    const int w    = tid >> 5;
    const int lane = tid & 31;
    const int u0   = blockIdx.x * UT;
    const int b0   = blockIdx.y * 32;
    const int grp  = blockIdx.y;
    const int b    = b0 + lane;
    const int uu0  = u0 + w*UW;

    for (int i = tid; i < 3*UT*UNITS; i += NTHR) {
        int k = i / (3*UT), c = i % (3*UT);
        int g = c / UT, lu = c % UT;
        sU[(lu*3 + g)*KP + k] = Ur[(size_t)k*(3*UNITS) + g*UNITS + u0 + lu];
    }
    for (int i = tid; i < 32*8; i += NTHR) {
        int bb = i >> 3, wd = i & 7;
        unsigned m = 0;
        for (int j = 0; j < 32; j++)
            m |= (tokens[(b0 + bb)*TT + wd*32 + j] != 0 ? 1u : 0u) << j;
        sMask[bb*8 + wd] = m;
    }
    {
        uint32_t sx0 = (uint32_t)__cvta_generic_to_shared(sX);
        for (int i = tid; i < 32*XS; i += NTHR) {
            int bb = i / XS, c = i % XS;
            int g = c / UT, lu = c % UT;
            cp_async4(sx0 + (uint32_t)i*4,
                      xw + ((size_t)0*BB + b0 + bb)*(size_t)(3*UNITS) + (size_t)g*UNITS + u0 + lu);
        }
        cp_commit();
    }

    float bz[UW], brr[UW], bh[UW];
#pragma unroll
    for (int j = 0; j < UW; j++) {
        bz[j]  = br[uu0 + j];
        brr[j] = br[UNITS + uu0 + j];
        bh[j]  = br[2*UNITS + uu0 + j];
    }

    const float* hrow = sH + lane*KP;
    const uint32_t sH_s = (uint32_t)__cvta_generic_to_shared(sH);
    const uint32_t sX_s = (uint32_t)__cvta_generic_to_shared(sX);

    for (int t = 0; t < TT; t++) {
        const float* hg = hping + (t & 1) * (BB*UNITS);
        float*       hn = hping + ((t + 1) & 1) * (BB*UNITS);
        const float* sXc = sX + (t & 1)*32*XS;

        for (int i = tid; i < 32*(UNITS/4); i += NTHR) {
            int bb = i / (UNITS/4), kk = i % (UNITS/4);
            cp_async16(sH_s + (uint32_t)(bb*KP + kk*4)*4,
                       hg + (size_t)(b0+bb)*UNITS + kk*4);
        }
        cp_commit();
        cp_wait0();
        __syncthreads();

        unsigned long long az[UW] = {}, ar[UW] = {}, ah[UW] = {};
#pragma unroll 4
        for (int k = 0; k < UNITS; k += 4) {
            ulonglong2 h2 = *reinterpret_cast<const ulonglong2*>(hrow + k);
#pragma unroll
            for (int j = 0; j < UW; j++) {
                const float* ub = sU + ((w*UW + j)*3)*KP + k;
                ulonglong2 uz = *reinterpret_cast<const ulonglong2*>(ub);
                ulonglong2 ur = *reinterpret_cast<const ulonglong2*>(ub + KP);
                ulonglong2 uh = *reinterpret_cast<const ulonglong2*>(ub + 2*KP);
                az[j] = fma2(h2.x, uz.x, az[j]); az[j] = fma2(h2.y, uz.y, az[j]);
                ar[j] = fma2(h2.x, ur.x, ar[j]); ar[j] = fma2(h2.y, ur.y, ar[j]);
                ah[j] = fma2(h2.x, uh.x, ah[j]); ah[j] = fma2(h2.y, uh.y, ah[j]);
            }
        }

        const int mk = (sMask[lane*8 + (t >> 5)] >> (t & 31)) & 1;
        float hv[UW];
#pragma unroll
        for (int j = 0; j < UW; j++) {
            float vz = hsum2(az[j]), vr = hsum2(ar[j]), vh = hsum2(ah[j]);
            int lu = w*UW + j;
            float xz = sXc[lane*XS + lu];
            float xr = sXc[lane*XS + UT + lu];
            float xh = sXc[lane*XS + 2*UT + lu];
            float z  = 1.f / (1.f + __expf(-(xz + vz + bz[j])));
            float r  = 1.f / (1.f + __expf(-(xr + vr + brr[j])));
            float hh = tanhf(xh + r * (vh + bh[j]));
            float hold = hrow[uu0 + j];
            float hnew = z*hold + (1.f - z)*hh;
            hv[j] = mk ? hnew : hold;
        }
        if constexpr (UW == 2) {
            float2 v = make_float2(hv[0], hv[1]);
            *reinterpret_cast<float2*>(hn + (size_t)b*UNITS + uu0) = v;
            *reinterpret_cast<float2*>(out + ((size_t)b*TT + t)*UNITS + uu0) = v;
        } else {
            hn[(size_t)b*UNITS + uu0] = hv[0];
            out[((size_t)b*TT + t)*UNITS + uu0] = hv[0];
        }

        if (t + 1 < TT) {
            uint32_t dst = sX_s + (uint32_t)(((t+1) & 1)*32*XS)*4;
            for (int i = tid; i < 32*XS; i += NTHR) {
                int bb = i / XS, c = i % XS;
                int g = c / UT, lu = c % UT;
                cp_async4(dst + (uint32_t)i*4,
                          xw + ((size_t)(t+1)*BB + b0 + bb)*(size_t)(3*UNITS)
                             + (size_t)g*UNITS + u0 + lu);
            }
            cp_commit();
        }

        __syncthreads();
        if (tid == 0) {
            unsigned* c = cnt + grp*32;
            unsigned* g = gen + grp*32;
            unsigned target = (unsigned)(t + 1);
            unsigned arr;
            asm volatile("atom.release.gpu.global.add.u32 %0, [%1], 1;"
                         : "=r"(arr) : "l"(c) : "memory");
            if (arr == (unsigned)(GROUP_CTAS - 1)) {
                asm volatile("st.relaxed.gpu.global.u32 [%0], 0;" :: "l"(c) : "memory");
                asm volatile("st.release.gpu.global.u32 [%0], %1;" :: "l"(g), "r"(target) : "memory");
            } else {
                unsigned gv;
                do {
                    asm volatile("ld.acquire.gpu.global.u32 %0, [%1];"
                                 : "=r"(gv) : "l"(g) : "memory");
                } while (gv < target);
            }
        }
        __syncthreads();
    }
}

extern "C" void kernel_launch(void* const* d_in, const int* in_sizes, int n_in,
                              void* d_out, int out_size)
{
    const int*   tokens = (const int*)  d_in[0];
    const float* emb    = (const float*)d_in[1];
    const float* gamma  = (const float*)d_in[2];
    const float* beta   = (const float*)d_in[3];
    const float* mmean  = (const float*)d_in[4];
    const float* mvar   = (const float*)d_in[5];
    const float* W1     = (const float*)d_in[6];
    const float* Ur1    = (const float*)d_in[7];
    const float* b1     = (const float*)d_in[8];
    const float* W2     = (const float*)d_in[9];
    const float* Ur2    = (const float*)d_in[10];
    const float* b2     = (const float*)d_in[11];

    float* out  = (float*)d_out;
    float* out2 = out + OUT2_OFF;
    float* out1 = out + OUT1_OFF;
    float* h2o  = out + H2_OFF;
    float* h1o  = out + H1_OFF;

    void *p_xn, *p_xw1, *p_xw2, *p_h1, *p_h2, *p_c1, *p_g1, *p_c2, *p_g2;
    cudaGetSymbolAddress(&p_xn,  g_xn);
    cudaGetSymbolAddress(&p_xw1, g_xw1);
    cudaGetSymbolAddress(&p_xw2, g_xw2);
    cudaGetSymbolAddress(&p_h1,  g_h1);
    cudaGetSymbolAddress(&p_h2,  g_h2);
    cudaGetSymbolAddress(&p_c1,  g_cnt1);
    cudaGetSymbolAddress(&p_g1,  g_gen1);
    cudaGetSymbolAddress(&p_c2,  g_cnt2);
    cudaGetSymbolAddress(&p_g2,  g_gen2);
    float* xn  = (float*)p_xn;
    float* xw1 = (float*)p_xw1;
    float* xw2 = (float*)p_xw2;
    float* h1p = (float*)p_h1;
    float* h2p = (float*)p_h2;

    constexpr int L1_SMEM = (16*3*(NU1+4) + 32*(NU1+4) + 2*32*48) * 4 + 32*8*4;
    constexpr int L2_SMEM = (8*3*(NU2+4) + 32*(NU2+4) + 2*32*24) * 4 + 32*8*4;

    cudaFuncSetAttribute(gru_layer<NU1, 16, 2, 25>,
                         cudaFuncAttributeMaxDynamicSharedMemorySize, L1_SMEM);
    cudaFuncSetAttribute(gru_layer<NU2, 8, 1, 25>,
                         cudaFuncAttributeMaxDynamicSharedMemorySize, L2_SMEM);

    embed_bn<<<(BB*TT*EMBD + 255)/256, 256>>>(tokens, emb, gamma, beta, mmean, mvar);
    init_state<<<(2*BB*NU1 + 255)/256, 256>>>();

    // xw1 = xn @ W1 + b1[0]
    sgemm<false><<<dim3((3*NU1 + 63)/64, (BB*TT)/64), 256>>>(xn, W1, b1, xw1, 3*NU1, EMBD);

    gru_layer<NU1, 16, 2, 25><<<dim3(NU1/16, BB/32), 256, L1_SMEM>>>(
        xw1, Ur1, b1 + 3*NU1, tokens, out1, h1p, (unsigned*)p_c1, (unsigned*)p_g1);

    copy_h<<<(BB*NU1 + 255)/256, 256>>>(h1p, h1o, BB*NU1);   // T even -> final in buf 0

    // xw2 = out1 @ W2 + b2[0] (gather rows from out1 [b][t][400])
    sgemm<true><<<dim3((3*NU2 + 63)/64, (BB*TT)/64), 256>>>(out1, W2, b2, xw2, 3*NU2, NU1);

    gru_layer<NU2, 8, 1, 25><<<dim3(NU2/8, BB/32), 256, L2_SMEM>>>(
        xw2, Ur2, b2 + 3*NU2, tokens, out2, h2p, (unsigned*)p_c2, (unsigned*)p_g2);

    copy_h<<<(BB*NU2 + 255)/256, 256>>>(h2p, h2o, BB*NU2);
}

// round 9
// speedup vs baseline: 3.7654x; 1.0610x over previous
#include <cuda_runtime.h>
#include <cstdint>
#include <cstddef>

#define BB 128
#define TT 256
#define EMBD 200
#define NU1 400
#define NU2 200

// output layout: out2 | out1 | h2 | h1
#define OUT2_OFF 0
#define OUT1_OFF (BB*TT*NU2)
#define H2_OFF   (OUT1_OFF + BB*TT*NU1)
#define H1_OFF   (H2_OFF + BB*NU2)

__device__ float g_xn [(size_t)BB*TT*EMBD];
__device__ float g_xw1[(size_t)BB*TT*3*NU1];
__device__ float g_xw2[(size_t)BB*TT*3*NU2];
__device__ float g_o1t[(size_t)BB*TT*NU1];   // out1 transposed [t][u][b]
__device__ float g_o2t[(size_t)BB*TT*NU2];   // out2 transposed [t][u][b]
__device__ float g_h1 [2*BB*NU1];
__device__ float g_h2 [2*BB*NU2];
__device__ unsigned g_cnt1[4*32], g_gen1[4*32], g_cnt2[4*32], g_gen2[4*32];

// ---- cp.async helpers ----
__device__ __forceinline__ void cp_async4(uint32_t s, const void* g)
{
    asm volatile("cp.async.ca.shared.global [%0], [%1], 4;" :: "r"(s), "l"(g));
}
__device__ __forceinline__ void cp_async16(uint32_t s, const void* g)
{
    asm volatile("cp.async.cg.shared.global [%0], [%1], 16;" :: "r"(s), "l"(g));
}
__device__ __forceinline__ void cp_commit() { asm volatile("cp.async.commit_group;"); }
__device__ __forceinline__ void cp_wait0()  { asm volatile("cp.async.wait_all;"); }

// packed f32x2 ops (sm_10x)
__device__ __forceinline__ unsigned long long fma2(unsigned long long a, unsigned long long b,
                                                   unsigned long long c)
{
    unsigned long long d;
    asm("fma.rn.f32x2 %0, %1, %2, %3;" : "=l"(d) : "l"(a), "l"(b), "l"(c));
    return d;
}
__device__ __forceinline__ unsigned long long pack2(float lo, float hi)
{
    unsigned long long d;
    asm("mov.b64 %0, {%1, %2};" : "=l"(d) : "f"(lo), "f"(hi));
    return d;
}
__device__ __forceinline__ float hsum2(unsigned long long a)
{
    float2 f = *reinterpret_cast<float2*>(&a);
    return f.x + f.y;
}
__device__ __forceinline__ float2 unpack2(unsigned long long a)
{
    return *reinterpret_cast<float2*>(&a);
}

__global__ void embed_bn(const int* __restrict__ tokens, const float* __restrict__ emb,
                         const float* __restrict__ gamma, const float* __restrict__ beta,
                         const float* __restrict__ mmean, const float* __restrict__ mvar)
{
    int idx = blockIdx.x * blockDim.x + threadIdx.x;
    if (idx >= BB*TT*EMBD) return;
    int d = idx % EMBD;
    int m = idx / EMBD;              // m = t*128 + b
    int b = m & (BB-1), t = m >> 7;
    int tok = tokens[b*TT + t];
    float s = gamma[d] * rsqrtf(mvar[d] + 1e-3f);
    g_xn[idx] = (emb[(size_t)tok*EMBD + d] - mmean[d]) * s + beta[d];
}

__global__ void init_state()
{
    int i = blockIdx.x * blockDim.x + threadIdx.x;
    if (i < 2*BB*NU1) g_h1[i] = 0.f;
    if (i < 2*BB*NU2) g_h2[i] = 0.f;
    if (i < 4*32) { g_cnt1[i] = 0; g_gen1[i] = 0; g_cnt2[i] = 0; g_gen2[i] = 0; }
}

__global__ void copy_h(const float* __restrict__ src, float* __restrict__ dst, int n)
{
    int i = blockIdx.x * blockDim.x + threadIdx.x;
    if (i < n) dst[i] = src[i];
}

// transpose src [TT][U][BB] -> dst [BB][TT][U]; grid (TT, ceil(U/32), BB/32), block (32,8)
__global__ void transpose_tub(const float* __restrict__ src, float* __restrict__ dst, int U)
{
    __shared__ float s[32][33];
    int t = blockIdx.x, u0 = blockIdx.y*32, b0 = blockIdx.z*32;
    int xi = threadIdx.x, yj = threadIdx.y;
    for (int i = yj; i < 32; i += 8) {
        int u = u0 + i;
        if (u < U) s[i][xi] = src[((size_t)t*U + u)*BB + b0 + xi];
    }
    __syncthreads();
    for (int i = yj; i < 32; i += 8) {
        int u = u0 + xi;
        if (u < U) dst[((size_t)(b0 + i)*TT + t)*U + u] = s[xi][i];
    }
}

// ---------------- SGEMM: C[M,N] = A @ B + bias, 128x128 tile, 8x8/thread, f32x2 ----------------
// ALAY=0: A is [M][K] row-major (M = 128*gridDim.y, K mult of 8)
// ALAY=1: A is [t][K][128] (t = blockIdx.y), i.e. transposed out1 scratch
template<int ALAY>
__global__ void __launch_bounds__(256, 2)
sgemm128(const float* __restrict__ A, const float* __restrict__ Bw,
         const float* __restrict__ bias, float* __restrict__ C, int N, int K)
{
    constexpr int AP = 132, BP = 132;
    __shared__ float As[2][8][AP];
    __shared__ float Bs[2][8][BP];
    const int tid = threadIdx.x;
    const int col0 = blockIdx.x * 128;
    const int row0 = blockIdx.y * 128;
    const int tx = tid & 15, ty = tid >> 4;

    // zero Bs (covers OOB columns permanently)
    for (int i = tid; i < 2*8*BP; i += 256) (&Bs[0][0][0])[i] = 0.f;
    __syncthreads();

    const int bkk = tid >> 5, bnq = (tid & 31) * 4;
    const int bgc = col0 + bnq;
    uint32_t bs_s0 = (uint32_t)__cvta_generic_to_shared(&Bs[0][bkk][bnq]);
    uint32_t bs_s1 = (uint32_t)__cvta_generic_to_shared(&Bs[1][bkk][bnq]);

    float4 rA;
    auto loadA = [&](int k0) {
        if (ALAY == 0) {
            int m = tid >> 1, kq = (tid & 1) * 4;
            rA = *reinterpret_cast<const float4*>(A + (size_t)(row0 + m)*K + k0 + kq);
        } else {
            int kk = tid >> 5, bq = (tid & 31) * 4;
            rA = *reinterpret_cast<const float4*>(A + ((size_t)blockIdx.y*K + k0 + kk)*128 + bq);
        }
    };
    auto stsA = [&](int buf) {
        if (ALAY == 0) {
            int m = tid >> 1, kq = (tid & 1) * 4;
            As[buf][kq+0][m] = rA.x; As[buf][kq+1][m] = rA.y;
            As[buf][kq+2][m] = rA.z; As[buf][kq+3][m] = rA.w;
        } else {
            int kk = tid >> 5, bq = (tid & 31) * 4;
            *reinterpret_cast<float4*>(&As[buf][kk][bq]) = rA;
        }
    };
    auto asyncB = [&](int k0, int buf) {
        if (bgc < N)
            cp_async16(buf ? bs_s1 : bs_s0, Bw + (size_t)(k0 + bkk)*N + bgc);
    };

    loadA(0);
    asyncB(0, 0);
    cp_commit();

    unsigned long long acc[4][8] = {};  // [row-pair][col: 0..3 -> tx*4+c, 4..7 -> 64+tx*4+c]

    const int NC = K / 8;
    for (int c = 0; c < NC; c++) {
        int buf = c & 1;
        cp_wait0();              // B(c) landed (only outstanding group)
        stsA(buf);
        __syncthreads();
        if (c + 1 < NC) {
            loadA((c+1)*8);
            asyncB((c+1)*8, buf ^ 1);
            cp_commit();
        }
#pragma unroll
        for (int kk = 0; kk < 8; kk++) {
            ulonglong2 a01 = *reinterpret_cast<const ulonglong2*>(&As[buf][kk][ty*8]);
            ulonglong2 a23 = *reinterpret_cast<const ulonglong2*>(&As[buf][kk][ty*8 + 4]);
            float4 b0 = *reinterpret_cast<const float4*>(&Bs[buf][kk][tx*4]);
            float4 b1 = *reinterpret_cast<const float4*>(&Bs[buf][kk][64 + tx*4]);
            unsigned long long ap[4] = {a01.x, a01.y, a23.x, a23.y};
            unsigned long long bd[8];
            bd[0] = pack2(b0.x, b0.x); bd[1] = pack2(b0.y, b0.y);
            bd[2] = pack2(b0.z, b0.z); bd[3] = pack2(b0.w, b0.w);
            bd[4] = pack2(b1.x, b1.x); bd[5] = pack2(b1.y, b1.y);
            bd[6] = pack2(b1.z, b1.z); bd[7] = pack2(b1.w, b1.w);
#pragma unroll
            for (int r = 0; r < 4; r++)
#pragma unroll
                for (int cc = 0; cc < 8; cc++)
                    acc[r][cc] = fma2(ap[r], bd[cc], acc[r][cc]);
        }
        __syncthreads();
    }

#pragma unroll
    for (int r = 0; r < 4; r++) {
        size_t gr = row0 + ty*8 + r*2;
#pragma unroll
        for (int cc = 0; cc < 8; cc++) {
            int gc = col0 + (cc < 4 ? tx*4 + cc : 64 + tx*4 + (cc - 4));
            if (gc < N) {
                float2 v = unpack2(acc[r][cc]);
                float bv = bias[gc];
                C[gr*N + gc]       = v.x + bv;
                C[(gr + 1)*N + gc] = v.y + bv;
            }
        }
    }
}

// ---------------- persistent GRU layer (R8-identical except out stores -> [t][u][b]) ----------------
template<int UNITS, int UT, int UW, int GROUP_CTAS>
__global__ void __launch_bounds__(32*UT/UW, 1)
gru_layer(const float* __restrict__ xw, const float* __restrict__ Ur,
          const float* __restrict__ br, const int* __restrict__ tokens,
          float* __restrict__ outT, float* __restrict__ hping,
          unsigned* cnt, unsigned* gen)
{
    constexpr int NTHR = 32*UT/UW;
    constexpr int KP = UNITS + 4;
    constexpr int XS = 3*UT;
    extern __shared__ float sm[];
    float*    sU    = sm;
    float*    sH    = sU + UT*3*KP;
    float*    sX    = sH + 32*KP;
    unsigned* sMask = (unsigned*)(sX + 2*32*XS);

    const int tid  = threadIdx.x;
    const int w    = tid >> 5;
    const int lane = tid & 31;
    const int u0   = blockIdx.x * UT;
    const int b0   = blockIdx.y * 32;
    const int grp  = blockIdx.y;
    const int b    = b0 + lane;
    const int uu0  = u0 + w*UW;

    for (int i = tid; i < 3*UT*UNITS; i += NTHR) {
        int k = i / (3*UT), c = i % (3*UT);
        int g = c / UT, lu = c % UT;
        sU[(lu*3 + g)*KP + k] = Ur[(size_t)k*(3*UNITS) + g*UNITS + u0 + lu];
    }
    for (int i = tid; i < 32*8; i += NTHR) {
        int bb = i >> 3, wd = i & 7;
        unsigned m = 0;
        for (int j = 0; j < 32; j++)
            m |= (tokens[(b0 + bb)*TT + wd*32 + j] != 0 ? 1u : 0u) << j;
        sMask[bb*8 + wd] = m;
    }
    {
        uint32_t sx0 = (uint32_t)__cvta_generic_to_shared(sX);
        for (int i = tid; i < 32*XS; i += NTHR) {
            int bb = i / XS, c = i % XS;
            int g = c / UT, lu = c % UT;
            cp_async4(sx0 + (uint32_t)i*4,
                      xw + ((size_t)0*BB + b0 + bb)*(size_t)(3*UNITS) + (size_t)g*UNITS + u0 + lu);
        }
        cp_commit();
    }

    float bz[UW], brr[UW], bh[UW];
#pragma unroll
    for (int j = 0; j < UW; j++) {
        bz[j]  = br[uu0 + j];
        brr[j] = br[UNITS + uu0 + j];
        bh[j]  = br[2*UNITS + uu0 + j];
    }

    const float* hrow = sH + lane*KP;
    const uint32_t sH_s = (uint32_t)__cvta_generic_to_shared(sH);
    const uint32_t sX_s = (uint32_t)__cvta_generic_to_shared(sX);

    for (int t = 0; t < TT; t++) {
        const float* hg = hping + (t & 1) * (BB*UNITS);
        float*       hn = hping + ((t + 1) & 1) * (BB*UNITS);
        const float* sXc = sX + (t & 1)*32*XS;

        for (int i = tid; i < 32*(UNITS/4); i += NTHR) {
            int bb = i / (UNITS/4), kk = i % (UNITS/4);
            cp_async16(sH_s + (uint32_t)(bb*KP + kk*4)*4,
                       hg + (size_t)(b0+bb)*UNITS + kk*4);
        }
        cp_commit();
        cp_wait0();
        __syncthreads();

        unsigned long long az[UW] = {}, ar[UW] = {}, ah[UW] = {};
#pragma unroll 4
        for (int k = 0; k < UNITS; k += 4) {
            ulonglong2 h2 = *reinterpret_cast<const ulonglong2*>(hrow + k);
#pragma unroll
            for (int j = 0; j < UW; j++) {
                const float* ub = sU + ((w*UW + j)*3)*KP + k;
                ulonglong2 uz = *reinterpret_cast<const ulonglong2*>(ub);
                ulonglong2 ur = *reinterpret_cast<const ulonglong2*>(ub + KP);
                ulonglong2 uh = *reinterpret_cast<const ulonglong2*>(ub + 2*KP);
                az[j] = fma2(h2.x, uz.x, az[j]); az[j] = fma2(h2.y, uz.y, az[j]);
                ar[j] = fma2(h2.x, ur.x, ar[j]); ar[j] = fma2(h2.y, ur.y, ar[j]);
                ah[j] = fma2(h2.x, uh.x, ah[j]); ah[j] = fma2(h2.y, uh.y, ah[j]);
            }
        }

        const int mk = (sMask[lane*8 + (t >> 5)] >> (t & 31)) & 1;
        float hv[UW];
#pragma unroll
        for (int j = 0; j < UW; j++) {
            float vz = hsum2(az[j]), vr = hsum2(ar[j]), vh = hsum2(ah[j]);
            int lu = w*UW + j;
            float xz = sXc[lane*XS + lu];
            float xr = sXc[lane*XS + UT + lu];
            float xh = sXc[lane*XS + 2*UT + lu];
            float z  = 1.f / (1.f + __expf(-(xz + vz + bz[j])));
            float r  = 1.f / (1.f + __expf(-(xr + vr + brr[j])));
            float hh = tanhf(xh + r * (vh + bh[j]));
            float hold = hrow[uu0 + j];
            float hnew = z*hold + (1.f - z)*hh;
            hv[j] = mk ? hnew : hold;
        }
        if constexpr (UW == 2) {
            float2 v = make_float2(hv[0], hv[1]);
            *reinterpret_cast<float2*>(hn + (size_t)b*UNITS + uu0) = v;
            outT[((size_t)t*UNITS + uu0    )*BB + b] = hv[0];
            outT[((size_t)t*UNITS + uu0 + 1)*BB + b] = hv[1];
        } else {
            hn[(size_t)b*UNITS + uu0] = hv[0];
            outT[((size_t)t*UNITS + uu0)*BB + b] = hv[0];
        }

        if (t + 1 < TT) {
            uint32_t dst = sX_s + (uint32_t)(((t+1) & 1)*32*XS)*4;
            for (int i = tid; i < 32*XS; i += NTHR) {
                int bb = i / XS, c = i % XS;
                int g = c / UT, lu = c % UT;
                cp_async4(dst + (uint32_t)i*4,
                          xw + ((size_t)(t+1)*BB + b0 + bb)*(size_t)(3*UNITS)
                             + (size_t)g*UNITS + u0 + lu);
            }
            cp_commit();
        }

        __syncthreads();
        if (tid == 0) {
            unsigned* c = cnt + grp*32;
            unsigned* g = gen + grp*32;
            unsigned target = (unsigned)(t + 1);
            unsigned arr;
            asm volatile("atom.release.gpu.global.add.u32 %0, [%1], 1;"
                         : "=r"(arr) : "l"(c) : "memory");
            if (arr == (unsigned)(GROUP_CTAS - 1)) {
                asm volatile("st.relaxed.gpu.global.u32 [%0], 0;" :: "l"(c) : "memory");
                asm volatile("st.release.gpu.global.u32 [%0], %1;" :: "l"(g), "r"(target) : "memory");
            } else {
                unsigned gv;
                do {
                    asm volatile("ld.acquire.gpu.global.u32 %0, [%1];"
                                 : "=r"(gv) : "l"(g) : "memory");
                } while (gv < target);
            }
        }
        __syncthreads();
    }
}

extern "C" void kernel_launch(void* const* d_in, const int* in_sizes, int n_in,
                              void* d_out, int out_size)
{
    const int*   tokens = (const int*)  d_in[0];
    const float* emb    = (const float*)d_in[1];
    const float* gamma  = (const float*)d_in[2];
    const float* beta   = (const float*)d_in[3];
    const float* mmean  = (const float*)d_in[4];
    const float* mvar   = (const float*)d_in[5];
    const float* W1     = (const float*)d_in[6];
    const float* Ur1    = (const float*)d_in[7];
    const float* b1     = (const float*)d_in[8];
    const float* W2     = (const float*)d_in[9];
    const float* Ur2    = (const float*)d_in[10];
    const float* b2     = (const float*)d_in[11];

    float* out  = (float*)d_out;
    float* out2 = out + OUT2_OFF;
    float* out1 = out + OUT1_OFF;
    float* h2o  = out + H2_OFF;
    float* h1o  = out + H1_OFF;

    void *p_xn, *p_xw1, *p_xw2, *p_o1t, *p_o2t, *p_h1, *p_h2, *p_c1, *p_g1, *p_c2, *p_g2;
    cudaGetSymbolAddress(&p_xn,  g_xn);
    cudaGetSymbolAddress(&p_xw1, g_xw1);
    cudaGetSymbolAddress(&p_xw2, g_xw2);
    cudaGetSymbolAddress(&p_o1t, g_o1t);
    cudaGetSymbolAddress(&p_o2t, g_o2t);
    cudaGetSymbolAddress(&p_h1,  g_h1);
    cudaGetSymbolAddress(&p_h2,  g_h2);
    cudaGetSymbolAddress(&p_c1,  g_cnt1);
    cudaGetSymbolAddress(&p_g1,  g_gen1);
    cudaGetSymbolAddress(&p_c2,  g_cnt2);
    cudaGetSymbolAddress(&p_g2,  g_gen2);
    float* xn  = (float*)p_xn;
    float* xw1 = (float*)p_xw1;
    float* xw2 = (float*)p_xw2;
    float* o1t = (float*)p_o1t;
    float* o2t = (float*)p_o2t;
    float* h1p = (float*)p_h1;
    float* h2p = (float*)p_h2;

    constexpr int L1_SMEM = (16*3*(NU1+4) + 32*(NU1+4) + 2*32*48) * 4 + 32*8*4;
    constexpr int L2_SMEM = (8*3*(NU2+4) + 32*(NU2+4) + 2*32*24) * 4 + 32*8*4;

    cudaFuncSetAttribute(gru_layer<NU1, 16, 2, 25>,
                         cudaFuncAttributeMaxDynamicSharedMemorySize, L1_SMEM);
    cudaFuncSetAttribute(gru_layer<NU2, 8, 1, 25>,
                         cudaFuncAttributeMaxDynamicSharedMemorySize, L2_SMEM);

    embed_bn<<<(BB*TT*EMBD + 255)/256, 256>>>(tokens, emb, gamma, beta, mmean, mvar);
    init_state<<<(2*BB*NU1 + 255)/256, 256>>>();

    // xw1 = xn @ W1 + b1[0] : [32768,200] x [200,1200]
    sgemm128<0><<<dim3((3*NU1 + 127)/128, (BB*TT)/128), 256>>>(xn, W1, b1, xw1, 3*NU1, EMBD);

    gru_layer<NU1, 16, 2, 25><<<dim3(NU1/16, BB/32), 256, L1_SMEM>>>(
        xw1, Ur1, b1 + 3*NU1, tokens, o1t, h1p, (unsigned*)p_c1, (unsigned*)p_g1);

    copy_h<<<(BB*NU1 + 255)/256, 256>>>(h1p, h1o, BB*NU1);   // T even -> final in buf 0
    transpose_tub<<<dim3(TT, (NU1 + 31)/32, BB/32), dim3(32, 8)>>>(o1t, out1, NU1);

    // xw2 = o1t @ W2 + b2[0] : A layout [t][400][128]
    sgemm128<1><<<dim3((3*NU2 + 127)/128, (BB*TT)/128), 256>>>(o1t, W2, b2, xw2, 3*NU2, NU1);

    gru_layer<NU2, 8, 1, 25><<<dim3(NU2/8, BB/32), 256, L2_SMEM>>>(
        xw2, Ur2, b2 + 3*NU2, tokens, o2t, h2p, (unsigned*)p_c2, (unsigned*)p_g2);

    copy_h<<<(BB*NU2 + 255)/256, 256>>>(h2p, h2o, BB*NU2);
    transpose_tub<<<dim3(TT, (NU2 + 31)/32, BB/32), dim3(32, 8)>>>(o2t, out2, NU2);
}